// round 1
// baseline (speedup 1.0000x reference)
#include <cuda_runtime.h>
#include <math.h>
#include <stdint.h>

#define BB 2
#define SS 2048
#define DD 1024
#define HH 16
#define DH 64
#define FF 4096
#define MM (BB*SS)   // 4096 rows

// ---------------- scratch (device globals; no allocation allowed) ----------
__device__ float g_x1 [MM*DD];
__device__ float g_q  [MM*DD];
__device__ float g_k  [MM*DD];
__device__ float g_v  [MM*DD];
__device__ float g_att[(size_t)BB*HH*SS*SS];   // 536.9 MB
__device__ float g_avo[MM*DD];
__device__ float g_x2 [MM*DD];
__device__ float g_x3 [MM*DD];
__device__ float g_h1 [MM*FF];

// ---------------- LayerNorm: one block per row of 1024 ---------------------
__global__ __launch_bounds__(256) void ln_kernel(
    const float* __restrict__ X, const float* __restrict__ g,
    const float* __restrict__ be, float* __restrict__ Y)
{
    int row = blockIdx.x;
    size_t base = (size_t)row * DD;
    int tid = threadIdx.x;
    float4 v = *(const float4*)(X + base + tid * 4);
    float s = v.x + v.y + v.z + v.w;
    float q = v.x*v.x + v.y*v.y + v.z*v.z + v.w*v.w;

    __shared__ float rs[32], rq[32];
    #pragma unroll
    for (int o = 16; o > 0; o >>= 1) {
        s += __shfl_xor_sync(0xFFFFFFFF, s, o);
        q += __shfl_xor_sync(0xFFFFFFFF, q, o);
    }
    int lane = tid & 31, w = tid >> 5;
    if (lane == 0) { rs[w] = s; rq[w] = q; }
    __syncthreads();
    if (w == 0) {
        s = (lane < 8) ? rs[lane] : 0.f;
        q = (lane < 8) ? rq[lane] : 0.f;
        #pragma unroll
        for (int o = 4; o > 0; o >>= 1) {
            s += __shfl_xor_sync(0xFFFFFFFF, s, o);
            q += __shfl_xor_sync(0xFFFFFFFF, q, o);
        }
        if (lane == 0) { rs[0] = s; rq[0] = q; }
    }
    __syncthreads();
    float mean = rs[0] * (1.f / DD);
    float var  = rq[0] * (1.f / DD) - mean * mean;
    float rstd = rsqrtf(var + 1e-5f);

    float4 gv = *(const float4*)(g  + tid * 4);
    float4 bv = *(const float4*)(be + tid * 4);
    float4 o4;
    o4.x = (v.x - mean) * rstd * gv.x + bv.x;
    o4.y = (v.y - mean) * rstd * gv.y + bv.y;
    o4.z = (v.z - mean) * rstd * gv.z + bv.z;
    o4.w = (v.w - mean) * rstd * gv.w + bv.w;
    *(float4*)(Y + base + tid * 4) = o4;
}

// ---------------- generic SGEMM: C = epi((A@B + bias)*scale) ---------------
// A: MxK row-major, B: KxN row-major. 64x64 block tile, BK=16, 256 threads,
// 4x4 outputs/thread. A staged transposed in smem for LDS.128 reads.
template<bool BIAS, bool RELU, bool RES>
__global__ __launch_bounds__(256) void sgemm64(
    const float* __restrict__ A, const float* __restrict__ Bm,
    const float* __restrict__ bias, const float* __restrict__ res,
    float* __restrict__ C, int M, int N, int K, float scale)
{
    __shared__ float As[16][68];   // [k][m], padded for conflict-free stores
    __shared__ float Bs[16][64];   // [k][n]

    int tid = threadIdx.x;
    int tx = tid & 15, ty = tid >> 4;
    int row0 = blockIdx.y * 64, col0 = blockIdx.x * 64;

    int ar = tid >> 2;            // 0..63
    int ac = (tid & 3) << 2;      // 0,4,8,12
    int br = tid >> 4;            // 0..15
    int bc = (tid & 15) << 2;     // 0..60

    const float* Aptr = A  + (size_t)(row0 + ar) * K + ac;
    const float* Bptr = Bm + (size_t)br * N + col0 + bc;

    float acc[4][4] = {};

    for (int kb = 0; kb < K; kb += 16) {
        float4 a4 = *(const float4*)(Aptr + kb);
        float4 b4 = *(const float4*)(Bptr + (size_t)kb * N);
        As[ac+0][ar] = a4.x; As[ac+1][ar] = a4.y;
        As[ac+2][ar] = a4.z; As[ac+3][ar] = a4.w;
        *(float4*)&Bs[br][bc] = b4;
        __syncthreads();
        #pragma unroll
        for (int kk = 0; kk < 16; kk++) {
            float4 av = *(const float4*)&As[kk][ty << 2];
            float4 bv = *(const float4*)&Bs[kk][tx << 2];
            float a[4] = {av.x, av.y, av.z, av.w};
            float b[4] = {bv.x, bv.y, bv.z, bv.w};
            #pragma unroll
            for (int i = 0; i < 4; i++)
                #pragma unroll
                for (int j = 0; j < 4; j++)
                    acc[i][j] = fmaf(a[i], b[j], acc[i][j]);
        }
        __syncthreads();
    }

    #pragma unroll
    for (int i = 0; i < 4; i++) {
        int r = row0 + (ty << 2) + i;
        int c = col0 + (tx << 2);
        float o[4];
        #pragma unroll
        for (int j = 0; j < 4; j++) {
            float v = acc[i][j];
            if (BIAS) v += bias[c + j];
            v *= scale;
            if (RELU) v = fmaxf(v, 0.f);
            if (RES)  v += res[(size_t)r * N + c + j];
            o[j] = v;
        }
        *(float4*)(C + (size_t)r * N + c) =
            make_float4(o[0], o[1], o[2], o[3]);
    }
}

// ---------------- attention scores: qk + relative skew ---------------------
// att[b,h,s,t] = q[b,s,h,:]·k[b,t,h,:] + (t<=s ? q[b,s,h,:]·Er[S-1-s+t,:] : 0)
__global__ __launch_bounds__(256) void scores_kernel(
    const float* __restrict__ Q, const float* __restrict__ Kk,
    const float* __restrict__ Er, float* __restrict__ ATT)
{
    __shared__ float Qs[64][64];     // [d][s]
    __shared__ float UB[64 * 128];   // phase1: K [d][t] stride 64; phase2: Er [d][o] stride 128

    int tid = threadIdx.x;
    int tx = tid & 15, ty = tid >> 4;
    int t0 = blockIdx.x * 64, s0 = blockIdx.y * 64;
    int bh = blockIdx.z;
    int b = bh >> 4, h = bh & 15;

    const float* Qb = Q  + ((size_t)b * SS) * DD + h * DH;
    const float* Kb = Kk + ((size_t)b * SS) * DD + h * DH;

    // load Q & K tiles, transposed into smem
    #pragma unroll
    for (int it = 0; it < 4; it++) {
        int fid = it * 256 + tid;
        int r  = fid >> 4;
        int c4 = (fid & 15) << 2;
        float4 qv = *(const float4*)(Qb + (size_t)(s0 + r) * DD + c4);
        float4 kv = *(const float4*)(Kb + (size_t)(t0 + r) * DD + c4);
        Qs[c4+0][r] = qv.x; Qs[c4+1][r] = qv.y;
        Qs[c4+2][r] = qv.z; Qs[c4+3][r] = qv.w;
        UB[(c4+0)*64 + r] = kv.x; UB[(c4+1)*64 + r] = kv.y;
        UB[(c4+2)*64 + r] = kv.z; UB[(c4+3)*64 + r] = kv.w;
    }
    __syncthreads();

    float acc[4][4] = {};
    // phase 1: q·k over d=0..63
    #pragma unroll 16
    for (int d = 0; d < 64; d++) {
        float4 a4 = *(const float4*)&Qs[d][ty << 2];
        float4 b4 = *(const float4*)&UB[d * 64 + (tx << 2)];
        float a[4] = {a4.x, a4.y, a4.z, a4.w};
        float bb[4] = {b4.x, b4.y, b4.z, b4.w};
        #pragma unroll
        for (int i = 0; i < 4; i++)
            #pragma unroll
            for (int j = 0; j < 4; j++)
                acc[i][j] = fmaf(a[i], bb[j], acc[i][j]);
    }
    __syncthreads();

    // phase 2: load Er window [base, base+126]; zero-fill rows >= S (mask)
    int base = SS - 64 + t0 - s0;   // >= 0 always
    #pragma unroll
    for (int it = 0; it < 8; it++) {
        int fid = it * 256 + tid;
        int o  = fid >> 4;          // 0..127
        int c4 = (fid & 15) << 2;
        int row = base + o;
        float4 ev = make_float4(0.f, 0.f, 0.f, 0.f);
        if (o < 127 && row < SS)
            ev = *(const float4*)(Er + (size_t)row * DH + c4);
        UB[(c4+0)*128 + o] = ev.x; UB[(c4+1)*128 + o] = ev.y;
        UB[(c4+2)*128 + o] = ev.z; UB[(c4+3)*128 + o] = ev.w;
    }
    __syncthreads();

    // rel term: o = (t-t0)-(s-s0)+63 = oc + j - i,  oc = 63 + 4*(tx-ty)
    int oc = 63 + ((tx - ty) << 2);
    #pragma unroll 16
    for (int d = 0; d < 64; d++) {
        float4 a4 = *(const float4*)&Qs[d][ty << 2];
        float e[8];
        *(float4*)&e[0] = *(const float4*)&UB[d * 128 + oc - 3];
        *(float4*)&e[4] = *(const float4*)&UB[d * 128 + oc + 1];
        float a[4] = {a4.x, a4.y, a4.z, a4.w};
        #pragma unroll
        for (int i = 0; i < 4; i++)
            #pragma unroll
            for (int j = 0; j < 4; j++)
                acc[i][j] = fmaf(a[i], e[j - i + 3], acc[i][j]);
    }

    float* out = ATT + ((size_t)bh * SS + s0) * SS + t0;
    #pragma unroll
    for (int i = 0; i < 4; i++) {
        *(float4*)(out + (size_t)((ty << 2) + i) * SS + (tx << 2)) =
            make_float4(acc[i][0], acc[i][1], acc[i][2], acc[i][3]);
    }
}

// ---------------- in-place row softmax over 2048 ----------------------------
__global__ __launch_bounds__(256) void softmax_kernel(float* __restrict__ ATT)
{
    size_t row = blockIdx.x;
    float* p = ATT + row * SS;
    int tid = threadIdx.x;

    __shared__ float buf[SS];
    __shared__ float red[32];

    float4 v0 = *(const float4*)(p + tid * 4);
    float4 v1 = *(const float4*)(p + 1024 + tid * 4);
    float lm = fmaxf(fmaxf(fmaxf(v0.x, v0.y), fmaxf(v0.z, v0.w)),
                     fmaxf(fmaxf(v1.x, v1.y), fmaxf(v1.z, v1.w)));
    #pragma unroll
    for (int o = 16; o > 0; o >>= 1)
        lm = fmaxf(lm, __shfl_xor_sync(0xFFFFFFFF, lm, o));
    int lane = tid & 31, w = tid >> 5;
    if (lane == 0) red[w] = lm;
    __syncthreads();
    if (w == 0) {
        lm = (lane < 8) ? red[lane] : -1e30f;
        #pragma unroll
        for (int o = 4; o > 0; o >>= 1)
            lm = fmaxf(lm, __shfl_xor_sync(0xFFFFFFFF, lm, o));
        if (lane == 0) red[0] = lm;
    }
    __syncthreads();
    float m = red[0];

    float e0x = expf(v0.x - m), e0y = expf(v0.y - m), e0z = expf(v0.z - m), e0w = expf(v0.w - m);
    float e1x = expf(v1.x - m), e1y = expf(v1.y - m), e1z = expf(v1.z - m), e1w = expf(v1.w - m);
    *(float4*)(buf + tid * 4)        = make_float4(e0x, e0y, e0z, e0w);
    *(float4*)(buf + 1024 + tid * 4) = make_float4(e1x, e1y, e1z, e1w);
    float ls = e0x + e0y + e0z + e0w + e1x + e1y + e1z + e1w;
    #pragma unroll
    for (int o = 16; o > 0; o >>= 1)
        ls += __shfl_xor_sync(0xFFFFFFFF, ls, o);
    __syncthreads();           // red[] reuse
    if (lane == 0) red[w] = ls;
    __syncthreads();
    if (w == 0) {
        ls = (lane < 8) ? red[lane] : 0.f;
        #pragma unroll
        for (int o = 4; o > 0; o >>= 1)
            ls += __shfl_xor_sync(0xFFFFFFFF, ls, o);
        if (lane == 0) red[0] = ls;
    }
    __syncthreads();
    float inv = 1.f / red[0];

    float4 b0 = *(const float4*)(buf + tid * 4);
    float4 b1 = *(const float4*)(buf + 1024 + tid * 4);
    *(float4*)(p + tid * 4) = make_float4(b0.x*inv, b0.y*inv, b0.z*inv, b0.w*inv);
    *(float4*)(p + 1024 + tid * 4) = make_float4(b1.x*inv, b1.y*inv, b1.z*inv, b1.w*inv);
}

// ---------------- AV: out[b,s,h,:] = sum_t att[b,h,s,t] * v[b,t,h,:] --------
__global__ __launch_bounds__(256) void av_kernel(
    const float* __restrict__ ATT, const float* __restrict__ V,
    float* __restrict__ O)
{
    __shared__ float As[16][68];  // [t][s]
    __shared__ float Vs[16][64];  // [t][d]

    int tid = threadIdx.x;
    int tx = tid & 15, ty = tid >> 4;
    int s0 = blockIdx.x * 64;
    int bh = blockIdx.y;
    int b = bh >> 4, h = bh & 15;

    const float* attb = ATT + ((size_t)bh * SS + s0) * SS;
    const float* vb   = V + ((size_t)b * SS) * DD + h * DH;

    int ar = tid >> 2, ac = (tid & 3) << 2;
    int vr = tid >> 4, vc = (tid & 15) << 2;

    float acc[4][4] = {};
    for (int kb = 0; kb < SS; kb += 16) {
        float4 a4 = *(const float4*)(attb + (size_t)ar * SS + kb + ac);
        float4 v4 = *(const float4*)(vb + (size_t)(kb + vr) * DD + vc);
        As[ac+0][ar] = a4.x; As[ac+1][ar] = a4.y;
        As[ac+2][ar] = a4.z; As[ac+3][ar] = a4.w;
        *(float4*)&Vs[vr][vc] = v4;
        __syncthreads();
        #pragma unroll
        for (int kk = 0; kk < 16; kk++) {
            float4 av = *(const float4*)&As[kk][ty << 2];
            float4 bv = *(const float4*)&Vs[kk][tx << 2];
            float a[4] = {av.x, av.y, av.z, av.w};
            float b2[4] = {bv.x, bv.y, bv.z, bv.w};
            #pragma unroll
            for (int i = 0; i < 4; i++)
                #pragma unroll
                for (int j = 0; j < 4; j++)
                    acc[i][j] = fmaf(a[i], b2[j], acc[i][j]);
        }
        __syncthreads();
    }

    float* ob = O + ((size_t)b * SS + s0) * DD + h * DH;
    #pragma unroll
    for (int i = 0; i < 4; i++) {
        *(float4*)(ob + (size_t)((ty << 2) + i) * DD + (tx << 2)) =
            make_float4(acc[i][0], acc[i][1], acc[i][2], acc[i][3]);
    }
}

// ---------------- launch ----------------------------------------------------
extern "C" void kernel_launch(void* const* d_in, const int* in_sizes, int n_in,
                              void* d_out, int out_size)
{
    (void)in_sizes; (void)n_in; (void)out_size;
    const float* x   = (const float*)d_in[0];
    const float* Wq  = (const float*)d_in[1];
    const float* bq  = (const float*)d_in[2];
    const float* Wk  = (const float*)d_in[3];
    const float* bk  = (const float*)d_in[4];
    const float* Wv  = (const float*)d_in[5];
    const float* bv  = (const float*)d_in[6];
    const float* Wo  = (const float*)d_in[7];
    const float* bo  = (const float*)d_in[8];
    const float* Er  = (const float*)d_in[9];
    const float* W1  = (const float*)d_in[10];
    const float* b1  = (const float*)d_in[11];
    const float* W2  = (const float*)d_in[12];
    const float* b2  = (const float*)d_in[13];
    const float* g1  = (const float*)d_in[14];
    const float* be1 = (const float*)d_in[15];
    const float* g2  = (const float*)d_in[16];
    const float* be2 = (const float*)d_in[17];
    float* y = (float*)d_out;

    float *px1, *pq, *pk, *pv, *patt, *pavo, *px2, *px3, *ph1;
    cudaGetSymbolAddress((void**)&px1,  g_x1);
    cudaGetSymbolAddress((void**)&pq,   g_q);
    cudaGetSymbolAddress((void**)&pk,   g_k);
    cudaGetSymbolAddress((void**)&pv,   g_v);
    cudaGetSymbolAddress((void**)&patt, g_att);
    cudaGetSymbolAddress((void**)&pavo, g_avo);
    cudaGetSymbolAddress((void**)&px2,  g_x2);
    cudaGetSymbolAddress((void**)&px3,  g_x3);
    cudaGetSymbolAddress((void**)&ph1,  g_h1);

    // x1 = LN(x)
    ln_kernel<<<MM, 256>>>(x, g1, be1, px1);
    // q = (x1@Wq+bq)/8 ; k ; v
    sgemm64<true,false,false><<<dim3(DD/64, MM/64), 256>>>(px1, Wq, bq, nullptr, pq, MM, DD, DD, 0.125f);
    sgemm64<true,false,false><<<dim3(DD/64, MM/64), 256>>>(px1, Wk, bk, nullptr, pk, MM, DD, DD, 1.f);
    sgemm64<true,false,false><<<dim3(DD/64, MM/64), 256>>>(px1, Wv, bv, nullptr, pv, MM, DD, DD, 1.f);
    // att = qk^T + skew(q Er^T)
    scores_kernel<<<dim3(SS/64, SS/64, BB*HH), 256>>>(pq, pk, Er, patt);
    // softmax rows
    softmax_kernel<<<BB*HH*SS, 256>>>(patt);
    // out = att @ v
    av_kernel<<<dim3(SS/64, BB*HH), 256>>>(patt, pv, pavo);
    // x2 = x1 + out@Wo + bo
    sgemm64<true,false,true><<<dim3(DD/64, MM/64), 256>>>(pavo, Wo, bo, px1, px2, MM, DD, DD, 1.f);
    // x3 = LN(x2)
    ln_kernel<<<MM, 256>>>(px2, g2, be2, px3);
    // h1 = relu(x3@W1+b1)
    sgemm64<true,true,false><<<dim3(FF/64, MM/64), 256>>>(px3, W1, b1, nullptr, ph1, MM, FF, DD, 1.f);
    // y = x3 + h1@W2 + b2
    sgemm64<true,false,true><<<dim3(DD/64, MM/64), 256>>>(ph1, W2, b2, px3, y, MM, DD, FF, 1.f);
}

// round 3
// speedup vs baseline: 1.4124x; 1.4124x over previous
#include <cuda_runtime.h>
#include <cuda_bf16.h>
#include <math.h>
#include <stdint.h>

#define BB 2
#define SS 2048
#define DD 1024
#define HH 16
#define DH 64
#define FF 4096
#define MM (BB*SS)   // 4096 rows

// ---------------- scratch (device globals; no allocation allowed) ----------
__device__ float g_x1 [MM*DD];
__device__ float g_q  [MM*DD];
__device__ float g_k  [MM*DD];
__device__ float g_v  [MM*DD];
__device__ float g_att[(size_t)BB*HH*SS*SS];   // 536.9 MB
__device__ float g_x2 [MM*DD];
__device__ float g_x3 [MM*DD];

__device__ __nv_bfloat16 g_x1h[MM*DD],  g_x1l[MM*DD];
__device__ __nv_bfloat16 g_x3h[MM*DD],  g_x3l[MM*DD];
__device__ __nv_bfloat16 g_avh[MM*DD],  g_avl[MM*DD];
__device__ __nv_bfloat16 g_h1h[(size_t)MM*FF], g_h1l[(size_t)MM*FF];
__device__ __nv_bfloat16 g_wqh[DD*DD], g_wql[DD*DD];
__device__ __nv_bfloat16 g_wkh[DD*DD], g_wkl[DD*DD];
__device__ __nv_bfloat16 g_wvh[DD*DD], g_wvl[DD*DD];
__device__ __nv_bfloat16 g_woh[DD*DD], g_wol[DD*DD];
__device__ __nv_bfloat16 g_w1h[(size_t)DD*FF], g_w1l[(size_t)DD*FF];
__device__ __nv_bfloat16 g_w2h[(size_t)DD*FF], g_w2l[(size_t)DD*FF];

// ======================= helpers ============================================
__device__ __forceinline__ uint32_t smem_u32(const void* p) {
    uint32_t a;
    asm("{ .reg .u64 t; cvta.to.shared.u64 t, %1; cvt.u32.u64 %0, t; }"
        : "=r"(a) : "l"(p));
    return a;
}
__device__ __forceinline__ void ldsm4(uint32_t* r, uint32_t addr) {
    asm volatile("ldmatrix.sync.aligned.m8n8.x4.shared.b16 {%0,%1,%2,%3}, [%4];"
        : "=r"(r[0]), "=r"(r[1]), "=r"(r[2]), "=r"(r[3]) : "r"(addr));
}
__device__ __forceinline__ void mma_bf16(float* c, const uint32_t* a, const uint32_t* b) {
    asm volatile("mma.sync.aligned.m16n8k16.row.col.f32.bf16.bf16.f32 "
        "{%0,%1,%2,%3}, {%4,%5,%6,%7}, {%8,%9}, {%0,%1,%2,%3};"
        : "+f"(c[0]), "+f"(c[1]), "+f"(c[2]), "+f"(c[3])
        : "r"(a[0]), "r"(a[1]), "r"(a[2]), "r"(a[3]), "r"(b[0]), "r"(b[1]));
}
__device__ __forceinline__ void split_bf16(float v, __nv_bfloat16& h, __nv_bfloat16& l) {
    h = __float2bfloat16(v);
    l = __float2bfloat16(v - __bfloat162float(h));
}

// ================== weight transpose + bf16 split: [K][N]->[N][K] ===========
__global__ __launch_bounds__(256) void convBT(
    const float* __restrict__ W, __nv_bfloat16* __restrict__ Th,
    __nv_bfloat16* __restrict__ Tl, int K, int N)
{
    __shared__ float ts[32][33];
    int n0 = blockIdx.x * 32, k0 = blockIdx.y * 32;
    int tx = threadIdx.x & 31, ty = threadIdx.x >> 5;   // 32 x 8
    #pragma unroll
    for (int i = 0; i < 4; i++)
        ts[ty + 8*i][tx] = W[(size_t)(k0 + ty + 8*i) * N + n0 + tx];
    __syncthreads();
    #pragma unroll
    for (int i = 0; i < 4; i++) {
        int n = ty + 8*i;
        float v = ts[tx][n];
        __nv_bfloat16 h, l; split_bf16(v, h, l);
        size_t o = (size_t)(n0 + n) * K + k0 + tx;
        Th[o] = h; Tl[o] = l;
    }
}

// ---------------- LayerNorm: fp32 out + bf16 hi/lo split --------------------
__global__ __launch_bounds__(256) void ln_kernel(
    const float* __restrict__ X, const float* __restrict__ g,
    const float* __restrict__ be, float* __restrict__ Y,
    __nv_bfloat16* __restrict__ Yh, __nv_bfloat16* __restrict__ Yl)
{
    int row = blockIdx.x;
    size_t base = (size_t)row * DD;
    int tid = threadIdx.x;
    float4 v = *(const float4*)(X + base + tid * 4);
    float s = v.x + v.y + v.z + v.w;
    float q = v.x*v.x + v.y*v.y + v.z*v.z + v.w*v.w;

    __shared__ float rs[32], rq[32];
    #pragma unroll
    for (int o = 16; o > 0; o >>= 1) {
        s += __shfl_xor_sync(0xFFFFFFFF, s, o);
        q += __shfl_xor_sync(0xFFFFFFFF, q, o);
    }
    int lane = tid & 31, w = tid >> 5;
    if (lane == 0) { rs[w] = s; rq[w] = q; }
    __syncthreads();
    if (w == 0) {
        s = (lane < 8) ? rs[lane] : 0.f;
        q = (lane < 8) ? rq[lane] : 0.f;
        #pragma unroll
        for (int o = 4; o > 0; o >>= 1) {
            s += __shfl_xor_sync(0xFFFFFFFF, s, o);
            q += __shfl_xor_sync(0xFFFFFFFF, q, o);
        }
        if (lane == 0) { rs[0] = s; rq[0] = q; }
    }
    __syncthreads();
    float mean = rs[0] * (1.f / DD);
    float var  = rq[0] * (1.f / DD) - mean * mean;
    float rstd = rsqrtf(var + 1e-5f);

    float4 gv = *(const float4*)(g  + tid * 4);
    float4 bv = *(const float4*)(be + tid * 4);
    float4 o4;
    o4.x = (v.x - mean) * rstd * gv.x + bv.x;
    o4.y = (v.y - mean) * rstd * gv.y + bv.y;
    o4.z = (v.z - mean) * rstd * gv.z + bv.z;
    o4.w = (v.w - mean) * rstd * gv.w + bv.w;
    *(float4*)(Y + base + tid * 4) = o4;

    __nv_bfloat16 h0,l0,h1,l1,h2,l2,h3,l3;
    split_bf16(o4.x, h0, l0); split_bf16(o4.y, h1, l1);
    split_bf16(o4.z, h2, l2); split_bf16(o4.w, h3, l3);
    *(__nv_bfloat162*)(Yh + base + tid*4)     = __halves2bfloat162(h0, h1);
    *(__nv_bfloat162*)(Yh + base + tid*4 + 2) = __halves2bfloat162(h2, h3);
    *(__nv_bfloat162*)(Yl + base + tid*4)     = __halves2bfloat162(l0, l1);
    *(__nv_bfloat162*)(Yl + base + tid*4 + 2) = __halves2bfloat162(l2, l3);
}

// ============== mma.sync bf16-split GEMM: C = epi(A@B^T + bias) =============
// A (hi/lo): [M][K] bf16 row-major.  B (hi/lo): [N][K] bf16 row-major.
// CTA 128x128, 8 warps of 32x64, K chunk 64, smem rows padded to 144B.
// OUTM: 0 = f32, 1 = bf16 hi/lo pair.
#define RSTR 144
#define ASZ (128 * RSTR)          // 18432 B per array
#define SA_HI 0
#define SA_LO ASZ
#define SB_HI (2*ASZ)
#define SB_LO (3*ASZ)
#define GEMM_SMEM (4*ASZ)         // 73728 B

template<int OUTM, bool RELU, bool RES>
__global__ __launch_bounds__(256)
void gemm_mma(
    const __nv_bfloat16* __restrict__ Ah, const __nv_bfloat16* __restrict__ Al,
    const __nv_bfloat16* __restrict__ Bh, const __nv_bfloat16* __restrict__ Bl,
    const float* __restrict__ bias, const float* __restrict__ res,
    float* __restrict__ Cf, __nv_bfloat16* __restrict__ Ch,
    __nv_bfloat16* __restrict__ Cl, int N, int K, float scale)
{
    extern __shared__ char smem[];
    uint32_t sb = smem_u32(smem);
    int tid = threadIdx.x;
    int lane = tid & 31, wid = tid >> 5;
    int wm = wid & 3, wn = wid >> 2;          // warp tile: rows wm*32, cols wn*64
    int m0 = blockIdx.y * 128, n0 = blockIdx.x * 128;

    // ldmatrix per-thread source addresses (byte offsets into arrays)
    int aRow = wm * 32 + ((lane >> 3) & 1) * 8 + (lane & 7);
    uint32_t aOff = (uint32_t)aRow * RSTR + ((lane >> 4) & 1) * 16;
    int bRow = wn * 64 + ((lane >> 4) & 1) * 8 + (lane & 7);
    uint32_t bOff = (uint32_t)bRow * RSTR + ((lane >> 3) & 1) * 16;

    float acc[2][8][4] = {};

    const int chunks = K >> 6;
    for (int c = 0; c < chunks; c++) {
        size_t koff = (size_t)c * 64;
        // stage 128x64 hi/lo tiles of A and B
        #pragma unroll
        for (int i = 0; i < 4; i++) {
            int u = tid + i * 256;
            int row = u >> 3, seg = u & 7;
            uint32_t d = (uint32_t)row * RSTR + seg * 16;
            const uint4* pah = (const uint4*)(Ah + (size_t)(m0+row)*K + koff) + seg;
            const uint4* pal = (const uint4*)(Al + (size_t)(m0+row)*K + koff) + seg;
            const uint4* pbh = (const uint4*)(Bh + (size_t)(n0+row)*K + koff) + seg;
            const uint4* pbl = (const uint4*)(Bl + (size_t)(n0+row)*K + koff) + seg;
            *(uint4*)(smem + SA_HI + d) = *pah;
            *(uint4*)(smem + SA_LO + d) = *pal;
            *(uint4*)(smem + SB_HI + d) = *pbh;
            *(uint4*)(smem + SB_LO + d) = *pbl;
        }
        __syncthreads();

        #pragma unroll
        for (int kk = 0; kk < 4; kk++) {
            uint32_t kb = kk * 32;
            uint32_t ah[2][4], al[2][4];
            ldsm4(ah[0], sb + SA_HI + aOff + kb);
            ldsm4(ah[1], sb + SA_HI + aOff + 16*RSTR + kb);
            ldsm4(al[0], sb + SA_LO + aOff + kb);
            ldsm4(al[1], sb + SA_LO + aOff + 16*RSTR + kb);
            uint32_t bh[4][4], bl[4][4];
            #pragma unroll
            for (int jp = 0; jp < 4; jp++) {
                ldsm4(bh[jp], sb + SB_HI + bOff + (uint32_t)jp*16*RSTR + kb);
                ldsm4(bl[jp], sb + SB_LO + bOff + (uint32_t)jp*16*RSTR + kb);
            }
            #pragma unroll
            for (int im = 0; im < 2; im++)
                #pragma unroll
                for (int jn = 0; jn < 8; jn++) {
                    const uint32_t* ph = &bh[jn >> 1][(jn & 1) * 2];
                    const uint32_t* pl = &bl[jn >> 1][(jn & 1) * 2];
                    mma_bf16(acc[im][jn], ah[im], ph);
                    mma_bf16(acc[im][jn], ah[im], pl);
                    mma_bf16(acc[im][jn], al[im], ph);
                }
        }
        __syncthreads();
    }

    // epilogue: fragment -> gmem directly
    int r = lane >> 2, cc = (lane & 3) * 2;
    #pragma unroll
    for (int im = 0; im < 2; im++) {
        int rg0 = m0 + wm * 32 + im * 16 + r;
        #pragma unroll
        for (int jn = 0; jn < 8; jn++) {
            int col = n0 + wn * 64 + jn * 8 + cc;
            float2 bv = *(const float2*)(bias + col);
            float v0 = (acc[im][jn][0] + bv.x) * scale;
            float v1 = (acc[im][jn][1] + bv.y) * scale;
            float v2 = (acc[im][jn][2] + bv.x) * scale;
            float v3 = (acc[im][jn][3] + bv.y) * scale;
            if (RELU) {
                v0 = fmaxf(v0, 0.f); v1 = fmaxf(v1, 0.f);
                v2 = fmaxf(v2, 0.f); v3 = fmaxf(v3, 0.f);
            }
            size_t o0 = (size_t)rg0 * N + col;
            size_t o1 = (size_t)(rg0 + 8) * N + col;
            if (RES) {
                float2 r0 = *(const float2*)(res + o0);
                float2 r1 = *(const float2*)(res + o1);
                v0 += r0.x; v1 += r0.y; v2 += r1.x; v3 += r1.y;
            }
            if (OUTM == 0) {
                *(float2*)(Cf + o0) = make_float2(v0, v1);
                *(float2*)(Cf + o1) = make_float2(v2, v3);
            } else {
                __nv_bfloat16 h0,l0,h1,l1,h2,l2,h3,l3;
                split_bf16(v0, h0, l0); split_bf16(v1, h1, l1);
                split_bf16(v2, h2, l2); split_bf16(v3, h3, l3);
                *(__nv_bfloat162*)(Ch + o0) = __halves2bfloat162(h0, h1);
                *(__nv_bfloat162*)(Ch + o1) = __halves2bfloat162(h2, h3);
                *(__nv_bfloat162*)(Cl + o0) = __halves2bfloat162(l0, l1);
                *(__nv_bfloat162*)(Cl + o1) = __halves2bfloat162(l2, l3);
            }
        }
    }
}

// ---------------- attention scores: qk + relative skew ---------------------
__global__ __launch_bounds__(256) void scores_kernel(
    const float* __restrict__ Q, const float* __restrict__ Kk,
    const float* __restrict__ Er, float* __restrict__ ATT)
{
    __shared__ float Qs[64][64];
    __shared__ float UB[64 * 128];

    int tid = threadIdx.x;
    int tx = tid & 15, ty = tid >> 4;
    int t0 = blockIdx.x * 64, s0 = blockIdx.y * 64;
    int bh = blockIdx.z;
    int b = bh >> 4, h = bh & 15;

    const float* Qb = Q  + ((size_t)b * SS) * DD + h * DH;
    const float* Kb = Kk + ((size_t)b * SS) * DD + h * DH;

    #pragma unroll
    for (int it = 0; it < 4; it++) {
        int fid = it * 256 + tid;
        int r  = fid >> 4;
        int c4 = (fid & 15) << 2;
        float4 qv = *(const float4*)(Qb + (size_t)(s0 + r) * DD + c4);
        float4 kv = *(const float4*)(Kb + (size_t)(t0 + r) * DD + c4);
        Qs[c4+0][r] = qv.x; Qs[c4+1][r] = qv.y;
        Qs[c4+2][r] = qv.z; Qs[c4+3][r] = qv.w;
        UB[(c4+0)*64 + r] = kv.x; UB[(c4+1)*64 + r] = kv.y;
        UB[(c4+2)*64 + r] = kv.z; UB[(c4+3)*64 + r] = kv.w;
    }
    __syncthreads();

    float acc[4][4] = {};
    #pragma unroll 16
    for (int d = 0; d < 64; d++) {
        float4 a4 = *(const float4*)&Qs[d][ty << 2];
        float4 b4 = *(const float4*)&UB[d * 64 + (tx << 2)];
        float a[4] = {a4.x, a4.y, a4.z, a4.w};
        float bb[4] = {b4.x, b4.y, b4.z, b4.w};
        #pragma unroll
        for (int i = 0; i < 4; i++)
            #pragma unroll
            for (int j = 0; j < 4; j++)
                acc[i][j] = fmaf(a[i], bb[j], acc[i][j]);
    }
    __syncthreads();

    int base = SS - 64 + t0 - s0;
    #pragma unroll
    for (int it = 0; it < 8; it++) {
        int fid = it * 256 + tid;
        int o  = fid >> 4;
        int c4 = (fid & 15) << 2;
        int row = base + o;
        float4 ev = make_float4(0.f, 0.f, 0.f, 0.f);
        if (o < 127 && row < SS)
            ev = *(const float4*)(Er + (size_t)row * DH + c4);
        UB[(c4+0)*128 + o] = ev.x; UB[(c4+1)*128 + o] = ev.y;
        UB[(c4+2)*128 + o] = ev.z; UB[(c4+3)*128 + o] = ev.w;
    }
    __syncthreads();

    int oc = 63 + ((tx - ty) << 2);
    #pragma unroll 16
    for (int d = 0; d < 64; d++) {
        float4 a4 = *(const float4*)&Qs[d][ty << 2];
        float e[8];
        *(float4*)&e[0] = *(const float4*)&UB[d * 128 + oc - 3];
        *(float4*)&e[4] = *(const float4*)&UB[d * 128 + oc + 1];
        float a[4] = {a4.x, a4.y, a4.z, a4.w};
        #pragma unroll
        for (int i = 0; i < 4; i++)
            #pragma unroll
            for (int j = 0; j < 4; j++)
                acc[i][j] = fmaf(a[i], e[j - i + 3], acc[i][j]);
    }

    float* out = ATT + ((size_t)bh * SS + s0) * SS + t0;
    #pragma unroll
    for (int i = 0; i < 4; i++) {
        *(float4*)(out + (size_t)((ty << 2) + i) * SS + (tx << 2)) =
            make_float4(acc[i][0], acc[i][1], acc[i][2], acc[i][3]);
    }
}

// ---------------- in-place row softmax over 2048 ----------------------------
__global__ __launch_bounds__(256) void softmax_kernel(float* __restrict__ ATT)
{
    size_t row = blockIdx.x;
    float* p = ATT + row * SS;
    int tid = threadIdx.x;

    __shared__ float buf[SS];
    __shared__ float red[32];

    float4 v0 = *(const float4*)(p + tid * 4);
    float4 v1 = *(const float4*)(p + 1024 + tid * 4);
    float lm = fmaxf(fmaxf(fmaxf(v0.x, v0.y), fmaxf(v0.z, v0.w)),
                     fmaxf(fmaxf(v1.x, v1.y), fmaxf(v1.z, v1.w)));
    #pragma unroll
    for (int o = 16; o > 0; o >>= 1)
        lm = fmaxf(lm, __shfl_xor_sync(0xFFFFFFFF, lm, o));
    int lane = tid & 31, w = tid >> 5;
    if (lane == 0) red[w] = lm;
    __syncthreads();
    if (w == 0) {
        lm = (lane < 8) ? red[lane] : -1e30f;
        #pragma unroll
        for (int o = 4; o > 0; o >>= 1)
            lm = fmaxf(lm, __shfl_xor_sync(0xFFFFFFFF, lm, o));
        if (lane == 0) red[0] = lm;
    }
    __syncthreads();
    float m = red[0];

    float e0x = expf(v0.x - m), e0y = expf(v0.y - m), e0z = expf(v0.z - m), e0w = expf(v0.w - m);
    float e1x = expf(v1.x - m), e1y = expf(v1.y - m), e1z = expf(v1.z - m), e1w = expf(v1.w - m);
    *(float4*)(buf + tid * 4)        = make_float4(e0x, e0y, e0z, e0w);
    *(float4*)(buf + 1024 + tid * 4) = make_float4(e1x, e1y, e1z, e1w);
    float ls = e0x + e0y + e0z + e0w + e1x + e1y + e1z + e1w;
    #pragma unroll
    for (int o = 16; o > 0; o >>= 1)
        ls += __shfl_xor_sync(0xFFFFFFFF, ls, o);
    __syncthreads();
    if (lane == 0) red[w] = ls;
    __syncthreads();
    if (w == 0) {
        ls = (lane < 8) ? red[lane] : 0.f;
        #pragma unroll
        for (int o = 4; o > 0; o >>= 1)
            ls += __shfl_xor_sync(0xFFFFFFFF, ls, o);
        if (lane == 0) red[0] = ls;
    }
    __syncthreads();
    float inv = 1.f / red[0];

    float4 b0 = *(const float4*)(buf + tid * 4);
    float4 b1 = *(const float4*)(buf + 1024 + tid * 4);
    *(float4*)(p + tid * 4) = make_float4(b0.x*inv, b0.y*inv, b0.z*inv, b0.w*inv);
    *(float4*)(p + 1024 + tid * 4) = make_float4(b1.x*inv, b1.y*inv, b1.z*inv, b1.w*inv);
}

// ---------------- AV: out = att @ v (bf16 hi/lo output) ---------------------
__global__ __launch_bounds__(256) void av_kernel(
    const float* __restrict__ ATT, const float* __restrict__ V,
    __nv_bfloat16* __restrict__ Oh, __nv_bfloat16* __restrict__ Ol)
{
    __shared__ float As[16][68];
    __shared__ float Vs[16][64];

    int tid = threadIdx.x;
    int tx = tid & 15, ty = tid >> 4;
    int s0 = blockIdx.x * 64;
    int bh = blockIdx.y;
    int b = bh >> 4, hd = bh & 15;

    const float* attb = ATT + ((size_t)bh * SS + s0) * SS;
    const float* vb   = V + ((size_t)b * SS) * DD + hd * DH;

    int ar = tid >> 2, ac = (tid & 3) << 2;
    int vr = tid >> 4, vc = (tid & 15) << 2;

    float acc[4][4] = {};
    for (int kb = 0; kb < SS; kb += 16) {
        float4 a4 = *(const float4*)(attb + (size_t)ar * SS + kb + ac);
        float4 v4 = *(const float4*)(vb + (size_t)(kb + vr) * DD + vc);
        As[ac+0][ar] = a4.x; As[ac+1][ar] = a4.y;
        As[ac+2][ar] = a4.z; As[ac+3][ar] = a4.w;
        *(float4*)&Vs[vr][vc] = v4;
        __syncthreads();
        #pragma unroll
        for (int kk = 0; kk < 16; kk++) {
            float4 av = *(const float4*)&As[kk][ty << 2];
            float4 bv = *(const float4*)&Vs[kk][tx << 2];
            float a[4] = {av.x, av.y, av.z, av.w};
            float b2[4] = {bv.x, bv.y, bv.z, bv.w};
            #pragma unroll
            for (int i = 0; i < 4; i++)
                #pragma unroll
                for (int j = 0; j < 4; j++)
                    acc[i][j] = fmaf(a[i], b2[j], acc[i][j]);
        }
        __syncthreads();
    }

    #pragma unroll
    for (int i = 0; i < 4; i++) {
        size_t ob = ((size_t)b * SS + s0 + (ty << 2) + i) * DD + hd * DH + (tx << 2);
        #pragma unroll
        for (int j = 0; j < 4; j++) {
            __nv_bfloat16 hb, lb; split_bf16(acc[i][j], hb, lb);
            Oh[ob + j] = hb; Ol[ob + j] = lb;
        }
    }
}

// ---------------- launch ----------------------------------------------------
extern "C" void kernel_launch(void* const* d_in, const int* in_sizes, int n_in,
                              void* d_out, int out_size)
{
    (void)in_sizes; (void)n_in; (void)out_size;
    const float* x   = (const float*)d_in[0];
    const float* Wq  = (const float*)d_in[1];
    const float* bq  = (const float*)d_in[2];
    const float* Wk  = (const float*)d_in[3];
    const float* bk  = (const float*)d_in[4];
    const float* Wv  = (const float*)d_in[5];
    const float* bv  = (const float*)d_in[6];
    const float* Wo  = (const float*)d_in[7];
    const float* bo  = (const float*)d_in[8];
    const float* Er  = (const float*)d_in[9];
    const float* W1  = (const float*)d_in[10];
    const float* b1  = (const float*)d_in[11];
    const float* W2  = (const float*)d_in[12];
    const float* b2  = (const float*)d_in[13];
    const float* g1  = (const float*)d_in[14];
    const float* be1 = (const float*)d_in[15];
    const float* g2  = (const float*)d_in[16];
    const float* be2 = (const float*)d_in[17];
    float* y = (float*)d_out;

    float *px1, *pq, *pk, *pv, *patt, *px2, *px3;
    cudaGetSymbolAddress((void**)&px1,  g_x1);
    cudaGetSymbolAddress((void**)&pq,   g_q);
    cudaGetSymbolAddress((void**)&pk,   g_k);
    cudaGetSymbolAddress((void**)&pv,   g_v);
    cudaGetSymbolAddress((void**)&patt, g_att);
    cudaGetSymbolAddress((void**)&px2,  g_x2);
    cudaGetSymbolAddress((void**)&px3,  g_x3);

    __nv_bfloat16 *x1h,*x1l,*x3h,*x3l,*avh,*avl,*h1h,*h1l;
    __nv_bfloat16 *wqh,*wql,*wkh,*wkl,*wvh,*wvl,*woh,*wol,*w1h,*w1l,*w2h,*w2l;
    cudaGetSymbolAddress((void**)&x1h, g_x1h); cudaGetSymbolAddress((void**)&x1l, g_x1l);
    cudaGetSymbolAddress((void**)&x3h, g_x3h); cudaGetSymbolAddress((void**)&x3l, g_x3l);
    cudaGetSymbolAddress((void**)&avh, g_avh); cudaGetSymbolAddress((void**)&avl, g_avl);
    cudaGetSymbolAddress((void**)&h1h, g_h1h); cudaGetSymbolAddress((void**)&h1l, g_h1l);
    cudaGetSymbolAddress((void**)&wqh, g_wqh); cudaGetSymbolAddress((void**)&wql, g_wql);
    cudaGetSymbolAddress((void**)&wkh, g_wkh); cudaGetSymbolAddress((void**)&wkl, g_wkl);
    cudaGetSymbolAddress((void**)&wvh, g_wvh); cudaGetSymbolAddress((void**)&wvl, g_wvl);
    cudaGetSymbolAddress((void**)&woh, g_woh); cudaGetSymbolAddress((void**)&wol, g_wol);
    cudaGetSymbolAddress((void**)&w1h, g_w1h); cudaGetSymbolAddress((void**)&w1l, g_w1l);
    cudaGetSymbolAddress((void**)&w2h, g_w2h); cudaGetSymbolAddress((void**)&w2l, g_w2l);

    cudaFuncSetAttribute(gemm_mma<0,false,false>, cudaFuncAttributeMaxDynamicSharedMemorySize, GEMM_SMEM);
    cudaFuncSetAttribute(gemm_mma<0,false,true>,  cudaFuncAttributeMaxDynamicSharedMemorySize, GEMM_SMEM);
    cudaFuncSetAttribute(gemm_mma<1,true,false>,  cudaFuncAttributeMaxDynamicSharedMemorySize, GEMM_SMEM);

    // weight transpose + split (per-launch, deterministic)
    convBT<<<dim3(DD/32, DD/32), 256>>>(Wq, wqh, wql, DD, DD);
    convBT<<<dim3(DD/32, DD/32), 256>>>(Wk, wkh, wkl, DD, DD);
    convBT<<<dim3(DD/32, DD/32), 256>>>(Wv, wvh, wvl, DD, DD);
    convBT<<<dim3(DD/32, DD/32), 256>>>(Wo, woh, wol, DD, DD);
    convBT<<<dim3(FF/32, DD/32), 256>>>(W1, w1h, w1l, DD, FF);
    convBT<<<dim3(DD/32, FF/32), 256>>>(W2, w2h, w2l, FF, DD);

    // x1 = LN(x) (+ bf16 split)
    ln_kernel<<<MM, 256>>>(x, g1, be1, px1, x1h, x1l);
    // q/k/v
    gemm_mma<0,false,false><<<dim3(DD/128, MM/128), 256, GEMM_SMEM>>>(
        x1h, x1l, wqh, wql, bq, nullptr, pq, nullptr, nullptr, DD, DD, 0.125f);
    gemm_mma<0,false,false><<<dim3(DD/128, MM/128), 256, GEMM_SMEM>>>(
        x1h, x1l, wkh, wkl, bk, nullptr, pk, nullptr, nullptr, DD, DD, 1.f);
    gemm_mma<0,false,false><<<dim3(DD/128, MM/128), 256, GEMM_SMEM>>>(
        x1h, x1l, wvh, wvl, bv, nullptr, pv, nullptr, nullptr, DD, DD, 1.f);
    // attention
    scores_kernel<<<dim3(SS/64, SS/64, BB*HH), 256>>>(pq, pk, Er, patt);
    softmax_kernel<<<BB*HH*SS, 256>>>(patt);
    av_kernel<<<dim3(SS/64, BB*HH), 256>>>(patt, pv, avh, avl);
    // x2 = x1 + av@Wo + bo
    gemm_mma<0,false,true><<<dim3(DD/128, MM/128), 256, GEMM_SMEM>>>(
        avh, avl, woh, wol, bo, px1, px2, nullptr, nullptr, DD, DD, 1.f);
    // x3 = LN(x2)
    ln_kernel<<<MM, 256>>>(px2, g2, be2, px3, x3h, x3l);
    // h1 = relu(x3@W1+b1) -> bf16 pair
    gemm_mma<1,true,false><<<dim3(FF/128, MM/128), 256, GEMM_SMEM>>>(
        x3h, x3l, w1h, w1l, b1, nullptr, nullptr, h1h, h1l, FF, DD, 1.f);
    // y = x3 + h1@W2 + b2
    gemm_mma<0,false,true><<<dim3(DD/128, MM/128), 256, GEMM_SMEM>>>(
        h1h, h1l, w2h, w2l, b2, px3, y, nullptr, nullptr, DD, FF, 1.f);
}

// round 4
// speedup vs baseline: 2.5799x; 1.8266x over previous
#include <cuda_runtime.h>
#include <cuda_bf16.h>
#include <math.h>
#include <stdint.h>

#define BB 2
#define SS 2048
#define DD 1024
#define HH 16
#define DH 64
#define FF 4096
#define MM (BB*SS)   // 4096 rows

// ---------------- scratch (device globals; no allocation allowed) ----------
__device__ float g_x1 [MM*DD];
__device__ float g_att[(size_t)BB*HH*SS*SS];   // 536.9 MB logits/probs
__device__ float g_rel[(size_t)BB*HH*SS*SS];   // 536.9 MB q@Er^T
__device__ float g_x2 [MM*DD];
__device__ float g_x3 [MM*DD];

__device__ __nv_bfloat16 g_x1h[MM*DD],  g_x1l[MM*DD];
__device__ __nv_bfloat16 g_x3h[MM*DD],  g_x3l[MM*DD];
__device__ __nv_bfloat16 g_qh [MM*DD],  g_ql [MM*DD];
__device__ __nv_bfloat16 g_kh [MM*DD],  g_kl [MM*DD];
__device__ __nv_bfloat16 g_vh [MM*DD],  g_vl [MM*DD];
__device__ __nv_bfloat16 g_avh[MM*DD],  g_avl[MM*DD];
__device__ __nv_bfloat16 g_h1h[(size_t)MM*FF], g_h1l[(size_t)MM*FF];
__device__ __nv_bfloat16 g_erh[SS*DH], g_erl[SS*DH];
__device__ __nv_bfloat16 g_wqh[DD*DD], g_wql[DD*DD];
__device__ __nv_bfloat16 g_wkh[DD*DD], g_wkl[DD*DD];
__device__ __nv_bfloat16 g_wvh[DD*DD], g_wvl[DD*DD];
__device__ __nv_bfloat16 g_woh[DD*DD], g_wol[DD*DD];
__device__ __nv_bfloat16 g_w1h[(size_t)DD*FF], g_w1l[(size_t)DD*FF];
__device__ __nv_bfloat16 g_w2h[(size_t)DD*FF], g_w2l[(size_t)DD*FF];

// ======================= helpers ============================================
__device__ __forceinline__ uint32_t smem_u32(const void* p) {
    uint32_t a;
    asm("{ .reg .u64 t; cvta.to.shared.u64 t, %1; cvt.u32.u64 %0, t; }"
        : "=r"(a) : "l"(p));
    return a;
}
__device__ __forceinline__ void ldsm4(uint32_t* r, uint32_t addr) {
    asm volatile("ldmatrix.sync.aligned.m8n8.x4.shared.b16 {%0,%1,%2,%3}, [%4];"
        : "=r"(r[0]), "=r"(r[1]), "=r"(r[2]), "=r"(r[3]) : "r"(addr));
}
__device__ __forceinline__ void ldsm4t(uint32_t* r, uint32_t addr) {
    asm volatile("ldmatrix.sync.aligned.m8n8.x4.trans.shared.b16 {%0,%1,%2,%3}, [%4];"
        : "=r"(r[0]), "=r"(r[1]), "=r"(r[2]), "=r"(r[3]) : "r"(addr));
}
__device__ __forceinline__ void mma_bf16(float* c, const uint32_t* a, const uint32_t* b) {
    asm volatile("mma.sync.aligned.m16n8k16.row.col.f32.bf16.bf16.f32 "
        "{%0,%1,%2,%3}, {%4,%5,%6,%7}, {%8,%9}, {%0,%1,%2,%3};"
        : "+f"(c[0]), "+f"(c[1]), "+f"(c[2]), "+f"(c[3])
        : "r"(a[0]), "r"(a[1]), "r"(a[2]), "r"(a[3]), "r"(b[0]), "r"(b[1]));
}
__device__ __forceinline__ void split_bf16(float v, __nv_bfloat16& h, __nv_bfloat16& l) {
    h = __float2bfloat16(v);
    l = __float2bfloat16(v - __bfloat162float(h));
}

#define RSTR 144

// ================== weight transpose + bf16 split: [K][N]->[N][K] ===========
__global__ __launch_bounds__(256) void convBT(
    const float* __restrict__ W, __nv_bfloat16* __restrict__ Th,
    __nv_bfloat16* __restrict__ Tl, int K, int N)
{
    __shared__ float ts[32][33];
    int n0 = blockIdx.x * 32, k0 = blockIdx.y * 32;
    int tx = threadIdx.x & 31, ty = threadIdx.x >> 5;
    #pragma unroll
    for (int i = 0; i < 4; i++)
        ts[ty + 8*i][tx] = W[(size_t)(k0 + ty + 8*i) * N + n0 + tx];
    __syncthreads();
    #pragma unroll
    for (int i = 0; i < 4; i++) {
        int n = ty + 8*i;
        float v = ts[tx][n];
        __nv_bfloat16 h, l; split_bf16(v, h, l);
        size_t o = (size_t)(n0 + n) * K + k0 + tx;
        Th[o] = h; Tl[o] = l;
    }
}

// -------- elementwise bf16 split (Er) ---------------------------------------
__global__ __launch_bounds__(256) void splitE(
    const float* __restrict__ X, __nv_bfloat16* __restrict__ Xh,
    __nv_bfloat16* __restrict__ Xl, int n)
{
    int i = blockIdx.x * 1024 + threadIdx.x * 4;
    if (i >= n) return;
    float4 v = *(const float4*)(X + i);
    __nv_bfloat16 h, l;
    split_bf16(v.x, h, l); Xh[i+0] = h; Xl[i+0] = l;
    split_bf16(v.y, h, l); Xh[i+1] = h; Xl[i+1] = l;
    split_bf16(v.z, h, l); Xh[i+2] = h; Xl[i+2] = l;
    split_bf16(v.w, h, l); Xh[i+3] = h; Xl[i+3] = l;
}

// ---------------- LayerNorm: fp32 out + bf16 hi/lo split --------------------
__global__ __launch_bounds__(256) void ln_kernel(
    const float* __restrict__ X, const float* __restrict__ g,
    const float* __restrict__ be, float* __restrict__ Y,
    __nv_bfloat16* __restrict__ Yh, __nv_bfloat16* __restrict__ Yl)
{
    int row = blockIdx.x;
    size_t base = (size_t)row * DD;
    int tid = threadIdx.x;
    float4 v = *(const float4*)(X + base + tid * 4);
    float s = v.x + v.y + v.z + v.w;
    float q = v.x*v.x + v.y*v.y + v.z*v.z + v.w*v.w;

    __shared__ float rs[32], rq[32];
    #pragma unroll
    for (int o = 16; o > 0; o >>= 1) {
        s += __shfl_xor_sync(0xFFFFFFFF, s, o);
        q += __shfl_xor_sync(0xFFFFFFFF, q, o);
    }
    int lane = tid & 31, w = tid >> 5;
    if (lane == 0) { rs[w] = s; rq[w] = q; }
    __syncthreads();
    if (w == 0) {
        s = (lane < 8) ? rs[lane] : 0.f;
        q = (lane < 8) ? rq[lane] : 0.f;
        #pragma unroll
        for (int o = 4; o > 0; o >>= 1) {
            s += __shfl_xor_sync(0xFFFFFFFF, s, o);
            q += __shfl_xor_sync(0xFFFFFFFF, q, o);
        }
        if (lane == 0) { rs[0] = s; rq[0] = q; }
    }
    __syncthreads();
    float mean = rs[0] * (1.f / DD);
    float var  = rq[0] * (1.f / DD) - mean * mean;
    float rstd = rsqrtf(var + 1e-5f);

    float4 gv = *(const float4*)(g  + tid * 4);
    float4 bv = *(const float4*)(be + tid * 4);
    float4 o4;
    o4.x = (v.x - mean) * rstd * gv.x + bv.x;
    o4.y = (v.y - mean) * rstd * gv.y + bv.y;
    o4.z = (v.z - mean) * rstd * gv.z + bv.z;
    o4.w = (v.w - mean) * rstd * gv.w + bv.w;
    *(float4*)(Y + base + tid * 4) = o4;

    __nv_bfloat16 h0,l0,h1,l1,h2,l2,h3,l3;
    split_bf16(o4.x, h0, l0); split_bf16(o4.y, h1, l1);
    split_bf16(o4.z, h2, l2); split_bf16(o4.w, h3, l3);
    *(__nv_bfloat162*)(Yh + base + tid*4)     = __halves2bfloat162(h0, h1);
    *(__nv_bfloat162*)(Yh + base + tid*4 + 2) = __halves2bfloat162(h2, h3);
    *(__nv_bfloat162*)(Yl + base + tid*4)     = __halves2bfloat162(l0, l1);
    *(__nv_bfloat162*)(Yl + base + tid*4 + 2) = __halves2bfloat162(l2, l3);
}

// ============== mma.sync bf16-split GEMM: C = epi(A@B^T + bias) =============
#define ASZ (128 * RSTR)
#define SA_HI 0
#define SA_LO ASZ
#define SB_HI (2*ASZ)
#define SB_LO (3*ASZ)
#define GEMM_SMEM (4*ASZ)         // 73728 B

template<int OUTM, bool RELU, bool RES>
__global__ __launch_bounds__(256)
void gemm_mma(
    const __nv_bfloat16* __restrict__ Ah, const __nv_bfloat16* __restrict__ Al,
    const __nv_bfloat16* __restrict__ Bh, const __nv_bfloat16* __restrict__ Bl,
    const float* __restrict__ bias, const float* __restrict__ res,
    float* __restrict__ Cf, __nv_bfloat16* __restrict__ Ch,
    __nv_bfloat16* __restrict__ Cl, int N, int K, float scale)
{
    extern __shared__ char smem[];
    uint32_t sb = smem_u32(smem);
    int tid = threadIdx.x;
    int lane = tid & 31, wid = tid >> 5;
    int wm = wid & 3, wn = wid >> 2;
    int m0 = blockIdx.y * 128, n0 = blockIdx.x * 128;

    int aRow = wm * 32 + ((lane >> 3) & 1) * 8 + (lane & 7);
    uint32_t aOff = (uint32_t)aRow * RSTR + ((lane >> 4) & 1) * 16;
    int bRow = wn * 64 + ((lane >> 4) & 1) * 8 + (lane & 7);
    uint32_t bOff = (uint32_t)bRow * RSTR + ((lane >> 3) & 1) * 16;

    float acc[2][8][4] = {};

    const int chunks = K >> 6;
    for (int c = 0; c < chunks; c++) {
        size_t koff = (size_t)c * 64;
        #pragma unroll
        for (int i = 0; i < 4; i++) {
            int u = tid + i * 256;
            int row = u >> 3, seg = u & 7;
            uint32_t d = (uint32_t)row * RSTR + seg * 16;
            *(uint4*)(smem + SA_HI + d) = *((const uint4*)(Ah + (size_t)(m0+row)*K + koff) + seg);
            *(uint4*)(smem + SA_LO + d) = *((const uint4*)(Al + (size_t)(m0+row)*K + koff) + seg);
            *(uint4*)(smem + SB_HI + d) = *((const uint4*)(Bh + (size_t)(n0+row)*K + koff) + seg);
            *(uint4*)(smem + SB_LO + d) = *((const uint4*)(Bl + (size_t)(n0+row)*K + koff) + seg);
        }
        __syncthreads();

        #pragma unroll
        for (int kk = 0; kk < 4; kk++) {
            uint32_t kb = kk * 32;
            uint32_t ah[2][4], al[2][4];
            ldsm4(ah[0], sb + SA_HI + aOff + kb);
            ldsm4(ah[1], sb + SA_HI + aOff + 16*RSTR + kb);
            ldsm4(al[0], sb + SA_LO + aOff + kb);
            ldsm4(al[1], sb + SA_LO + aOff + 16*RSTR + kb);
            uint32_t bh[4][4], bl[4][4];
            #pragma unroll
            for (int jp = 0; jp < 4; jp++) {
                ldsm4(bh[jp], sb + SB_HI + bOff + (uint32_t)jp*16*RSTR + kb);
                ldsm4(bl[jp], sb + SB_LO + bOff + (uint32_t)jp*16*RSTR + kb);
            }
            #pragma unroll
            for (int im = 0; im < 2; im++)
                #pragma unroll
                for (int jn = 0; jn < 8; jn++) {
                    const uint32_t* ph = &bh[jn >> 1][(jn & 1) * 2];
                    const uint32_t* pl = &bl[jn >> 1][(jn & 1) * 2];
                    mma_bf16(acc[im][jn], ah[im], ph);
                    mma_bf16(acc[im][jn], ah[im], pl);
                    mma_bf16(acc[im][jn], al[im], ph);
                }
        }
        __syncthreads();
    }

    int r = lane >> 2, cc = (lane & 3) * 2;
    #pragma unroll
    for (int im = 0; im < 2; im++) {
        int rg0 = m0 + wm * 32 + im * 16 + r;
        #pragma unroll
        for (int jn = 0; jn < 8; jn++) {
            int col = n0 + wn * 64 + jn * 8 + cc;
            float2 bv = *(const float2*)(bias + col);
            float v0 = (acc[im][jn][0] + bv.x) * scale;
            float v1 = (acc[im][jn][1] + bv.y) * scale;
            float v2 = (acc[im][jn][2] + bv.x) * scale;
            float v3 = (acc[im][jn][3] + bv.y) * scale;
            if (RELU) {
                v0 = fmaxf(v0, 0.f); v1 = fmaxf(v1, 0.f);
                v2 = fmaxf(v2, 0.f); v3 = fmaxf(v3, 0.f);
            }
            size_t o0 = (size_t)rg0 * N + col;
            size_t o1 = (size_t)(rg0 + 8) * N + col;
            if (RES) {
                float2 r0 = *(const float2*)(res + o0);
                float2 r1 = *(const float2*)(res + o1);
                v0 += r0.x; v1 += r0.y; v2 += r1.x; v3 += r1.y;
            }
            if (OUTM == 0) {
                *(float2*)(Cf + o0) = make_float2(v0, v1);
                *(float2*)(Cf + o1) = make_float2(v2, v3);
            } else {
                __nv_bfloat16 h0,l0,h1,l1,h2,l2,h3,l3;
                split_bf16(v0, h0, l0); split_bf16(v1, h1, l1);
                split_bf16(v2, h2, l2); split_bf16(v3, h3, l3);
                *(__nv_bfloat162*)(Ch + o0) = __halves2bfloat162(h0, h1);
                *(__nv_bfloat162*)(Ch + o1) = __halves2bfloat162(h2, h3);
                *(__nv_bfloat162*)(Cl + o0) = __halves2bfloat162(l0, l1);
                *(__nv_bfloat162*)(Cl + o1) = __halves2bfloat162(l2, l3);
            }
        }
    }
}

// ========== batched qk^T MMA: out[bh][s][t] = A[s]·B[t]  (K = 64) ===========
// A: q (per b,h slice of [M][D]). B: k slice or Er [N][64].
template<bool SKIP>
__global__ __launch_bounds__(256)
void qk_mma(
    const __nv_bfloat16* __restrict__ Ah, const __nv_bfloat16* __restrict__ Al,
    const __nv_bfloat16* __restrict__ Bh, const __nv_bfloat16* __restrict__ Bl,
    float* __restrict__ out, int ldb, size_t bBatch, int bHead)
{
    int m0 = blockIdx.y * 128, n0 = blockIdx.x * 128;
    if (SKIP && (m0 + n0 + 255 < SS - 1)) return;   // unused lower-left tiles of R
    int bh = blockIdx.z;
    int b = bh >> 4, h = bh & 15;

    extern __shared__ char smem[];
    uint32_t sb = smem_u32(smem);
    int tid = threadIdx.x;
    int lane = tid & 31, wid = tid >> 5;
    int wm = wid & 3, wn = wid >> 2;

    const __nv_bfloat16* Ahp = Ah + ((size_t)b * SS) * DD + h * DH;
    const __nv_bfloat16* Alp = Al + ((size_t)b * SS) * DD + h * DH;
    const __nv_bfloat16* Bhp = Bh + (size_t)b * bBatch + (size_t)h * bHead;
    const __nv_bfloat16* Blp = Bl + (size_t)b * bBatch + (size_t)h * bHead;

    #pragma unroll
    for (int i = 0; i < 4; i++) {
        int u = tid + i * 256;
        int row = u >> 3, seg = u & 7;
        uint32_t d = (uint32_t)row * RSTR + seg * 16;
        *(uint4*)(smem + SA_HI + d) = *((const uint4*)(Ahp + (size_t)(m0+row)*DD) + seg);
        *(uint4*)(smem + SA_LO + d) = *((const uint4*)(Alp + (size_t)(m0+row)*DD) + seg);
        *(uint4*)(smem + SB_HI + d) = *((const uint4*)(Bhp + (size_t)(n0+row)*ldb) + seg);
        *(uint4*)(smem + SB_LO + d) = *((const uint4*)(Blp + (size_t)(n0+row)*ldb) + seg);
    }
    __syncthreads();

    int aRow = wm * 32 + ((lane >> 3) & 1) * 8 + (lane & 7);
    uint32_t aOff = (uint32_t)aRow * RSTR + ((lane >> 4) & 1) * 16;
    int bRow = wn * 64 + ((lane >> 4) & 1) * 8 + (lane & 7);
    uint32_t bOff = (uint32_t)bRow * RSTR + ((lane >> 3) & 1) * 16;

    float acc[2][8][4] = {};
    #pragma unroll
    for (int kk = 0; kk < 4; kk++) {
        uint32_t kb = kk * 32;
        uint32_t ah[2][4], al[2][4];
        ldsm4(ah[0], sb + SA_HI + aOff + kb);
        ldsm4(ah[1], sb + SA_HI + aOff + 16*RSTR + kb);
        ldsm4(al[0], sb + SA_LO + aOff + kb);
        ldsm4(al[1], sb + SA_LO + aOff + 16*RSTR + kb);
        uint32_t bhf[4][4], blf[4][4];
        #pragma unroll
        for (int jp = 0; jp < 4; jp++) {
            ldsm4(bhf[jp], sb + SB_HI + bOff + (uint32_t)jp*16*RSTR + kb);
            ldsm4(blf[jp], sb + SB_LO + bOff + (uint32_t)jp*16*RSTR + kb);
        }
        #pragma unroll
        for (int im = 0; im < 2; im++)
            #pragma unroll
            for (int jn = 0; jn < 8; jn++) {
                const uint32_t* ph = &bhf[jn >> 1][(jn & 1) * 2];
                const uint32_t* pl = &blf[jn >> 1][(jn & 1) * 2];
                mma_bf16(acc[im][jn], ah[im], ph);
                mma_bf16(acc[im][jn], ah[im], pl);
                mma_bf16(acc[im][jn], al[im], ph);
            }
    }

    float* ob = out + (size_t)bh * SS * SS;
    int r = lane >> 2, cc = (lane & 3) * 2;
    #pragma unroll
    for (int im = 0; im < 2; im++) {
        int rg0 = m0 + wm * 32 + im * 16 + r;
        #pragma unroll
        for (int jn = 0; jn < 8; jn++) {
            int col = n0 + wn * 64 + jn * 8 + cc;
            *(float2*)(ob + (size_t)rg0 * SS + col)      = make_float2(acc[im][jn][0], acc[im][jn][1]);
            *(float2*)(ob + (size_t)(rg0+8) * SS + col)  = make_float2(acc[im][jn][2], acc[im][jn][3]);
        }
    }
}

// ====== fused skew-add + softmax: p[t] = softmax(p[t] + (t<=s)R[s][S-1-s+t]) =
__global__ __launch_bounds__(256) void softmax_kernel(
    float* __restrict__ ATT, const float* __restrict__ REL)
{
    size_t row = blockIdx.x;
    int s = (int)(row & (SS - 1));
    float* p = ATT + row * SS;
    const float* rp = REL + row * SS + (SS - 1 - s);
    int tid = threadIdx.x;
    int t0 = tid * 8;

    float v[8];
    *(float4*)&v[0] = *(const float4*)(p + t0);
    *(float4*)&v[4] = *(const float4*)(p + t0 + 4);
    #pragma unroll
    for (int j = 0; j < 8; j++) {
        int t = t0 + j;
        if (t <= s) v[j] += __ldg(rp + t);
    }

    __shared__ float red[32];
    float lm = v[0];
    #pragma unroll
    for (int j = 1; j < 8; j++) lm = fmaxf(lm, v[j]);
    #pragma unroll
    for (int o = 16; o > 0; o >>= 1)
        lm = fmaxf(lm, __shfl_xor_sync(0xFFFFFFFF, lm, o));
    int lane = tid & 31, w = tid >> 5;
    if (lane == 0) red[w] = lm;
    __syncthreads();
    if (w == 0) {
        lm = (lane < 8) ? red[lane] : -1e30f;
        #pragma unroll
        for (int o = 4; o > 0; o >>= 1)
            lm = fmaxf(lm, __shfl_xor_sync(0xFFFFFFFF, lm, o));
        if (lane == 0) red[0] = lm;
    }
    __syncthreads();
    float m = red[0];

    float ls = 0.f;
    #pragma unroll
    for (int j = 0; j < 8; j++) { v[j] = expf(v[j] - m); ls += v[j]; }
    #pragma unroll
    for (int o = 16; o > 0; o >>= 1)
        ls += __shfl_xor_sync(0xFFFFFFFF, ls, o);
    __syncthreads();
    if (lane == 0) red[w] = ls;
    __syncthreads();
    if (w == 0) {
        ls = (lane < 8) ? red[lane] : 0.f;
        #pragma unroll
        for (int o = 4; o > 0; o >>= 1)
            ls += __shfl_xor_sync(0xFFFFFFFF, ls, o);
        if (lane == 0) red[0] = ls;
    }
    __syncthreads();
    float inv = 1.f / red[0];
    #pragma unroll
    for (int j = 0; j < 8; j++) v[j] *= inv;
    *(float4*)(p + t0)     = *(float4*)&v[0];
    *(float4*)(p + t0 + 4) = *(float4*)&v[4];
}

// ====== AV MMA: out[b,s,h,:] = att[bh,s,:] @ v[b,:,h,:], att split in-kernel =
#define AV_SA_HI 0
#define AV_SA_LO ASZ
#define AV_SV_HI (2*ASZ)
#define AV_SV_LO (2*ASZ + 64*RSTR)
#define AV_SMEM  (2*ASZ + 2*64*RSTR)   // 55296 B

__global__ __launch_bounds__(256)
void av_mma(
    const float* __restrict__ ATT,
    const __nv_bfloat16* __restrict__ Vh, const __nv_bfloat16* __restrict__ Vl,
    __nv_bfloat16* __restrict__ Oh, __nv_bfloat16* __restrict__ Ol)
{
    extern __shared__ char smem[];
    uint32_t sb = smem_u32(smem);
    int tid = threadIdx.x;
    int lane = tid & 31, wid = tid >> 5;
    int wm = wid & 3, wn = wid >> 2;       // warp: 32 s-rows, 32 d-cols
    int s0 = blockIdx.x * 128;
    int bh = blockIdx.y;
    int b = bh >> 4, h = bh & 15;

    const float* attb = ATT + ((size_t)bh * SS + s0) * SS;
    const __nv_bfloat16* vhb = Vh + ((size_t)b * SS) * DD + h * DH;
    const __nv_bfloat16* vlb = Vl + ((size_t)b * SS) * DD + h * DH;

    int aRow = wm * 32 + ((lane >> 3) & 1) * 8 + (lane & 7);
    uint32_t aOff = (uint32_t)aRow * RSTR + ((lane >> 4) & 1) * 16;
    uint32_t vKr = ((lane >> 3) & 1) * 8 + (lane & 7);
    uint32_t vCb = (uint32_t)wn * 64 + ((lane >> 4) & 1) * 16;

    float acc[2][4][4] = {};

    for (int c = 0; c < SS / 64; c++) {
        int t0 = c * 64;
        // stage att fp32 -> bf16 hi/lo split
        #pragma unroll
        for (int i = 0; i < 8; i++) {
            int u = tid + i * 256;
            int row = u >> 4, seg = u & 15;
            float4 f = *((const float4*)(attb + (size_t)row * SS + t0) + seg);
            __nv_bfloat16 h0,l0,h1,l1,h2,l2,h3,l3;
            split_bf16(f.x, h0, l0); split_bf16(f.y, h1, l1);
            split_bf16(f.z, h2, l2); split_bf16(f.w, h3, l3);
            uint32_t d = (uint32_t)row * RSTR + seg * 8;
            *(__nv_bfloat162*)(smem + AV_SA_HI + d)     = __halves2bfloat162(h0, h1);
            *(__nv_bfloat162*)(smem + AV_SA_HI + d + 4) = __halves2bfloat162(h2, h3);
            *(__nv_bfloat162*)(smem + AV_SA_LO + d)     = __halves2bfloat162(l0, l1);
            *(__nv_bfloat162*)(smem + AV_SA_LO + d + 4) = __halves2bfloat162(l2, l3);
        }
        // stage v tiles [t][d]
        #pragma unroll
        for (int i = 0; i < 2; i++) {
            int u = tid + i * 256;
            int row = u >> 3, seg = u & 7;
            uint32_t d = (uint32_t)row * RSTR + seg * 16;
            *(uint4*)(smem + AV_SV_HI + d) = *((const uint4*)(vhb + (size_t)(t0+row)*DD) + seg);
            *(uint4*)(smem + AV_SV_LO + d) = *((const uint4*)(vlb + (size_t)(t0+row)*DD) + seg);
        }
        __syncthreads();

        #pragma unroll
        for (int kk = 0; kk < 4; kk++) {
            uint32_t kb = kk * 32;
            uint32_t ah[2][4], al[2][4];
            ldsm4(ah[0], sb + AV_SA_HI + aOff + kb);
            ldsm4(ah[1], sb + AV_SA_HI + aOff + 16*RSTR + kb);
            ldsm4(al[0], sb + AV_SA_LO + aOff + kb);
            ldsm4(al[1], sb + AV_SA_LO + aOff + 16*RSTR + kb);
            uint32_t bhf[2][4], blf[2][4];
            uint32_t vRowOff = (uint32_t)(kk * 16 + vKr) * RSTR;
            #pragma unroll
            for (int jp = 0; jp < 2; jp++) {
                ldsm4t(bhf[jp], sb + AV_SV_HI + vRowOff + vCb + jp * 32);
                ldsm4t(blf[jp], sb + AV_SV_LO + vRowOff + vCb + jp * 32);
            }
            #pragma unroll
            for (int im = 0; im < 2; im++)
                #pragma unroll
                for (int jn = 0; jn < 4; jn++) {
                    const uint32_t* ph = &bhf[jn >> 1][(jn & 1) * 2];
                    const uint32_t* pl = &blf[jn >> 1][(jn & 1) * 2];
                    mma_bf16(acc[im][jn], ah[im], ph);
                    mma_bf16(acc[im][jn], ah[im], pl);
                    mma_bf16(acc[im][jn], al[im], ph);
                }
        }
        __syncthreads();
    }

    int r = lane >> 2, cc = (lane & 3) * 2;
    #pragma unroll
    for (int im = 0; im < 2; im++) {
        int rg0 = s0 + wm * 32 + im * 16 + r;
        #pragma unroll
        for (int jn = 0; jn < 4; jn++) {
            int col = h * DH + wn * 32 + jn * 8 + cc;
            size_t o0 = ((size_t)b * SS + rg0) * DD + col;
            size_t o1 = ((size_t)b * SS + rg0 + 8) * DD + col;
            __nv_bfloat16 h0,l0,h1,l1,h2,l2,h3,l3;
            split_bf16(acc[im][jn][0], h0, l0); split_bf16(acc[im][jn][1], h1, l1);
            split_bf16(acc[im][jn][2], h2, l2); split_bf16(acc[im][jn][3], h3, l3);
            *(__nv_bfloat162*)(Oh + o0) = __halves2bfloat162(h0, h1);
            *(__nv_bfloat162*)(Oh + o1) = __halves2bfloat162(h2, h3);
            *(__nv_bfloat162*)(Ol + o0) = __halves2bfloat162(l0, l1);
            *(__nv_bfloat162*)(Ol + o1) = __halves2bfloat162(l2, l3);
        }
    }
}

// ---------------- launch ----------------------------------------------------
extern "C" void kernel_launch(void* const* d_in, const int* in_sizes, int n_in,
                              void* d_out, int out_size)
{
    (void)in_sizes; (void)n_in; (void)out_size;
    const float* x   = (const float*)d_in[0];
    const float* Wq  = (const float*)d_in[1];
    const float* bq  = (const float*)d_in[2];
    const float* Wk  = (const float*)d_in[3];
    const float* bk  = (const float*)d_in[4];
    const float* Wv  = (const float*)d_in[5];
    const float* bv  = (const float*)d_in[6];
    const float* Wo  = (const float*)d_in[7];
    const float* bo  = (const float*)d_in[8];
    const float* Er  = (const float*)d_in[9];
    const float* W1  = (const float*)d_in[10];
    const float* b1  = (const float*)d_in[11];
    const float* W2  = (const float*)d_in[12];
    const float* b2  = (const float*)d_in[13];
    const float* g1  = (const float*)d_in[14];
    const float* be1 = (const float*)d_in[15];
    const float* g2  = (const float*)d_in[16];
    const float* be2 = (const float*)d_in[17];
    float* y = (float*)d_out;

    float *px1, *patt, *prel, *px2, *px3;
    cudaGetSymbolAddress((void**)&px1,  g_x1);
    cudaGetSymbolAddress((void**)&patt, g_att);
    cudaGetSymbolAddress((void**)&prel, g_rel);
    cudaGetSymbolAddress((void**)&px2,  g_x2);
    cudaGetSymbolAddress((void**)&px3,  g_x3);

    __nv_bfloat16 *x1h,*x1l,*x3h,*x3l,*qh,*ql,*kh,*kl,*vh,*vl,*avh,*avl,*h1h,*h1l,*erh,*erl;
    __nv_bfloat16 *wqh,*wql,*wkh,*wkl,*wvh,*wvl,*woh,*wol,*w1h,*w1l,*w2h,*w2l;
    cudaGetSymbolAddress((void**)&x1h, g_x1h); cudaGetSymbolAddress((void**)&x1l, g_x1l);
    cudaGetSymbolAddress((void**)&x3h, g_x3h); cudaGetSymbolAddress((void**)&x3l, g_x3l);
    cudaGetSymbolAddress((void**)&qh,  g_qh);  cudaGetSymbolAddress((void**)&ql,  g_ql);
    cudaGetSymbolAddress((void**)&kh,  g_kh);  cudaGetSymbolAddress((void**)&kl,  g_kl);
    cudaGetSymbolAddress((void**)&vh,  g_vh);  cudaGetSymbolAddress((void**)&vl,  g_vl);
    cudaGetSymbolAddress((void**)&avh, g_avh); cudaGetSymbolAddress((void**)&avl, g_avl);
    cudaGetSymbolAddress((void**)&h1h, g_h1h); cudaGetSymbolAddress((void**)&h1l, g_h1l);
    cudaGetSymbolAddress((void**)&erh, g_erh); cudaGetSymbolAddress((void**)&erl, g_erl);
    cudaGetSymbolAddress((void**)&wqh, g_wqh); cudaGetSymbolAddress((void**)&wql, g_wql);
    cudaGetSymbolAddress((void**)&wkh, g_wkh); cudaGetSymbolAddress((void**)&wkl, g_wkl);
    cudaGetSymbolAddress((void**)&wvh, g_wvh); cudaGetSymbolAddress((void**)&wvl, g_wvl);
    cudaGetSymbolAddress((void**)&woh, g_woh); cudaGetSymbolAddress((void**)&wol, g_wol);
    cudaGetSymbolAddress((void**)&w1h, g_w1h); cudaGetSymbolAddress((void**)&w1l, g_w1l);
    cudaGetSymbolAddress((void**)&w2h, g_w2h); cudaGetSymbolAddress((void**)&w2l, g_w2l);

    cudaFuncSetAttribute(gemm_mma<0,false,false>, cudaFuncAttributeMaxDynamicSharedMemorySize, GEMM_SMEM);
    cudaFuncSetAttribute(gemm_mma<0,false,true>,  cudaFuncAttributeMaxDynamicSharedMemorySize, GEMM_SMEM);
    cudaFuncSetAttribute(gemm_mma<1,false,false>, cudaFuncAttributeMaxDynamicSharedMemorySize, GEMM_SMEM);
    cudaFuncSetAttribute(gemm_mma<1,true,false>,  cudaFuncAttributeMaxDynamicSharedMemorySize, GEMM_SMEM);
    cudaFuncSetAttribute(qk_mma<false>, cudaFuncAttributeMaxDynamicSharedMemorySize, GEMM_SMEM);
    cudaFuncSetAttribute(qk_mma<true>,  cudaFuncAttributeMaxDynamicSharedMemorySize, GEMM_SMEM);
    cudaFuncSetAttribute(av_mma, cudaFuncAttributeMaxDynamicSharedMemorySize, AV_SMEM);

    // weight transpose + split
    convBT<<<dim3(DD/32, DD/32), 256>>>(Wq, wqh, wql, DD, DD);
    convBT<<<dim3(DD/32, DD/32), 256>>>(Wk, wkh, wkl, DD, DD);
    convBT<<<dim3(DD/32, DD/32), 256>>>(Wv, wvh, wvl, DD, DD);
    convBT<<<dim3(DD/32, DD/32), 256>>>(Wo, woh, wol, DD, DD);
    convBT<<<dim3(FF/32, DD/32), 256>>>(W1, w1h, w1l, DD, FF);
    convBT<<<dim3(DD/32, FF/32), 256>>>(W2, w2h, w2l, FF, DD);
    splitE<<<(SS*DH + 1023)/1024, 256>>>(Er, erh, erl, SS*DH);

    // x1 = LN(x)
    ln_kernel<<<MM, 256>>>(x, g1, be1, px1, x1h, x1l);
    // q/k/v -> bf16 hi/lo
    gemm_mma<1,false,false><<<dim3(DD/128, MM/128), 256, GEMM_SMEM>>>(
        x1h, x1l, wqh, wql, bq, nullptr, nullptr, qh, ql, DD, DD, 0.125f);
    gemm_mma<1,false,false><<<dim3(DD/128, MM/128), 256, GEMM_SMEM>>>(
        x1h, x1l, wkh, wkl, bk, nullptr, nullptr, kh, kl, DD, DD, 1.f);
    gemm_mma<1,false,false><<<dim3(DD/128, MM/128), 256, GEMM_SMEM>>>(
        x1h, x1l, wvh, wvl, bv, nullptr, nullptr, vh, vl, DD, DD, 1.f);
    // att = q@k^T ; rel = q@Er^T (skip unused tiles)
    qk_mma<false><<<dim3(SS/128, SS/128, BB*HH), 256, GEMM_SMEM>>>(
        qh, ql, kh, kl, patt, DD, (size_t)SS*DD, DH);
    qk_mma<true><<<dim3(SS/128, SS/128, BB*HH), 256, GEMM_SMEM>>>(
        qh, ql, erh, erl, prel, DH, 0, 0);
    // softmax(att + skew(rel))
    softmax_kernel<<<BB*HH*SS, 256>>>(patt, prel);
    // av = att @ v
    av_mma<<<dim3(SS/128, BB*HH), 256, AV_SMEM>>>(patt, vh, vl, avh, avl);
    // x2 = x1 + av@Wo + bo
    gemm_mma<0,false,true><<<dim3(DD/128, MM/128), 256, GEMM_SMEM>>>(
        avh, avl, woh, wol, bo, px1, px2, nullptr, nullptr, DD, DD, 1.f);
    // x3 = LN(x2)
    ln_kernel<<<MM, 256>>>(px2, g2, be2, px3, x3h, x3l);
    // h1 = relu(x3@W1+b1)
    gemm_mma<1,true,false><<<dim3(FF/128, MM/128), 256, GEMM_SMEM>>>(
        x3h, x3l, w1h, w1l, b1, nullptr, nullptr, h1h, h1l, FF, DD, 1.f);
    // y = x3 + h1@W2 + b2
    gemm_mma<0,false,true><<<dim3(DD/128, MM/128), 256, GEMM_SMEM>>>(
        h1h, h1l, w2h, w2l, b2, px3, y, nullptr, nullptr, DD, FF, 1.f);
}

// round 5
// speedup vs baseline: 2.7146x; 1.0522x over previous
#include <cuda_runtime.h>
#include <cuda_bf16.h>
#include <math.h>
#include <stdint.h>

#define BB 2
#define SS 2048
#define DD 1024
#define HH 16
#define DH 64
#define FF 4096
#define MM (BB*SS)   // 4096 rows

// ---------------- scratch (device globals; no allocation allowed) ----------
__device__ float g_x1 [MM*DD];
__device__ float g_rel[(size_t)BB*HH*SS*SS];   // q@Er^T (upper band tiles only)
__device__ float g_x2 [MM*DD];
__device__ float g_x3 [MM*DD];

__device__ __nv_bfloat16 g_x1h[MM*DD],  g_x1l[MM*DD];
__device__ __nv_bfloat16 g_x3h[MM*DD],  g_x3l[MM*DD];
__device__ __nv_bfloat16 g_qh [MM*DD],  g_ql [MM*DD];
__device__ __nv_bfloat16 g_kh [MM*DD],  g_kl [MM*DD];
__device__ __nv_bfloat16 g_vh [MM*DD],  g_vl [MM*DD];
__device__ __nv_bfloat16 g_avh[MM*DD],  g_avl[MM*DD];
__device__ __nv_bfloat16 g_h1h[(size_t)MM*FF], g_h1l[(size_t)MM*FF];
__device__ __nv_bfloat16 g_erh[SS*DH], g_erl[SS*DH];
__device__ __nv_bfloat16 g_wqh[DD*DD], g_wql[DD*DD];
__device__ __nv_bfloat16 g_wkh[DD*DD], g_wkl[DD*DD];
__device__ __nv_bfloat16 g_wvh[DD*DD], g_wvl[DD*DD];
__device__ __nv_bfloat16 g_woh[DD*DD], g_wol[DD*DD];
__device__ __nv_bfloat16 g_w1h[(size_t)DD*FF], g_w1l[(size_t)DD*FF];
__device__ __nv_bfloat16 g_w2h[(size_t)DD*FF], g_w2l[(size_t)DD*FF];

// ======================= helpers ============================================
__device__ __forceinline__ uint32_t smem_u32(const void* p) {
    uint32_t a;
    asm("{ .reg .u64 t; cvta.to.shared.u64 t, %1; cvt.u32.u64 %0, t; }"
        : "=r"(a) : "l"(p));
    return a;
}
__device__ __forceinline__ void ldsm4(uint32_t* r, uint32_t addr) {
    asm volatile("ldmatrix.sync.aligned.m8n8.x4.shared.b16 {%0,%1,%2,%3}, [%4];"
        : "=r"(r[0]), "=r"(r[1]), "=r"(r[2]), "=r"(r[3]) : "r"(addr));
}
__device__ __forceinline__ void ldsm4t(uint32_t* r, uint32_t addr) {
    asm volatile("ldmatrix.sync.aligned.m8n8.x4.trans.shared.b16 {%0,%1,%2,%3}, [%4];"
        : "=r"(r[0]), "=r"(r[1]), "=r"(r[2]), "=r"(r[3]) : "r"(addr));
}
__device__ __forceinline__ void mma_bf16(float* c, const uint32_t* a, const uint32_t* b) {
    asm volatile("mma.sync.aligned.m16n8k16.row.col.f32.bf16.bf16.f32 "
        "{%0,%1,%2,%3}, {%4,%5,%6,%7}, {%8,%9}, {%0,%1,%2,%3};"
        : "+f"(c[0]), "+f"(c[1]), "+f"(c[2]), "+f"(c[3])
        : "r"(a[0]), "r"(a[1]), "r"(a[2]), "r"(a[3]), "r"(b[0]), "r"(b[1]));
}
__device__ __forceinline__ void split_bf16(float v, __nv_bfloat16& h, __nv_bfloat16& l) {
    h = __float2bfloat16(v);
    l = __float2bfloat16(v - __bfloat162float(h));
}
__device__ __forceinline__ void pack_split(float x, float y, uint32_t& hi, uint32_t& lo) {
    __nv_bfloat16 xh = __float2bfloat16(x), yh = __float2bfloat16(y);
    __nv_bfloat16 xl = __float2bfloat16(x - __bfloat162float(xh));
    __nv_bfloat16 yl = __float2bfloat16(y - __bfloat162float(yh));
    __nv_bfloat162 a = __halves2bfloat162(xh, yh);
    __nv_bfloat162 b = __halves2bfloat162(xl, yl);
    hi = *(uint32_t*)&a; lo = *(uint32_t*)&b;
}

#define RSTR 144

// ================== weight transpose + bf16 split: [K][N]->[N][K] ===========
__global__ __launch_bounds__(256) void convBT(
    const float* __restrict__ W, __nv_bfloat16* __restrict__ Th,
    __nv_bfloat16* __restrict__ Tl, int K, int N)
{
    __shared__ float ts[32][33];
    int n0 = blockIdx.x * 32, k0 = blockIdx.y * 32;
    int tx = threadIdx.x & 31, ty = threadIdx.x >> 5;
    #pragma unroll
    for (int i = 0; i < 4; i++)
        ts[ty + 8*i][tx] = W[(size_t)(k0 + ty + 8*i) * N + n0 + tx];
    __syncthreads();
    #pragma unroll
    for (int i = 0; i < 4; i++) {
        int n = ty + 8*i;
        float v = ts[tx][n];
        __nv_bfloat16 h, l; split_bf16(v, h, l);
        size_t o = (size_t)(n0 + n) * K + k0 + tx;
        Th[o] = h; Tl[o] = l;
    }
}

// -------- elementwise bf16 split (Er) ---------------------------------------
__global__ __launch_bounds__(256) void splitE(
    const float* __restrict__ X, __nv_bfloat16* __restrict__ Xh,
    __nv_bfloat16* __restrict__ Xl, int n)
{
    int i = blockIdx.x * 1024 + threadIdx.x * 4;
    if (i >= n) return;
    float4 v = *(const float4*)(X + i);
    __nv_bfloat16 h, l;
    split_bf16(v.x, h, l); Xh[i+0] = h; Xl[i+0] = l;
    split_bf16(v.y, h, l); Xh[i+1] = h; Xl[i+1] = l;
    split_bf16(v.z, h, l); Xh[i+2] = h; Xl[i+2] = l;
    split_bf16(v.w, h, l); Xh[i+3] = h; Xl[i+3] = l;
}

// ---------------- LayerNorm: fp32 out + bf16 hi/lo split --------------------
__global__ __launch_bounds__(256) void ln_kernel(
    const float* __restrict__ X, const float* __restrict__ g,
    const float* __restrict__ be, float* __restrict__ Y,
    __nv_bfloat16* __restrict__ Yh, __nv_bfloat16* __restrict__ Yl)
{
    int row = blockIdx.x;
    size_t base = (size_t)row * DD;
    int tid = threadIdx.x;
    float4 v = *(const float4*)(X + base + tid * 4);
    float s = v.x + v.y + v.z + v.w;
    float q = v.x*v.x + v.y*v.y + v.z*v.z + v.w*v.w;

    __shared__ float rs[32], rq[32];
    #pragma unroll
    for (int o = 16; o > 0; o >>= 1) {
        s += __shfl_xor_sync(0xFFFFFFFF, s, o);
        q += __shfl_xor_sync(0xFFFFFFFF, q, o);
    }
    int lane = tid & 31, w = tid >> 5;
    if (lane == 0) { rs[w] = s; rq[w] = q; }
    __syncthreads();
    if (w == 0) {
        s = (lane < 8) ? rs[lane] : 0.f;
        q = (lane < 8) ? rq[lane] : 0.f;
        #pragma unroll
        for (int o = 4; o > 0; o >>= 1) {
            s += __shfl_xor_sync(0xFFFFFFFF, s, o);
            q += __shfl_xor_sync(0xFFFFFFFF, q, o);
        }
        if (lane == 0) { rs[0] = s; rq[0] = q; }
    }
    __syncthreads();
    float mean = rs[0] * (1.f / DD);
    float var  = rq[0] * (1.f / DD) - mean * mean;
    float rstd = rsqrtf(var + 1e-5f);

    float4 gv = *(const float4*)(g  + tid * 4);
    float4 bv = *(const float4*)(be + tid * 4);
    float4 o4;
    o4.x = (v.x - mean) * rstd * gv.x + bv.x;
    o4.y = (v.y - mean) * rstd * gv.y + bv.y;
    o4.z = (v.z - mean) * rstd * gv.z + bv.z;
    o4.w = (v.w - mean) * rstd * gv.w + bv.w;
    *(float4*)(Y + base + tid * 4) = o4;

    __nv_bfloat16 h0,l0,h1,l1,h2,l2,h3,l3;
    split_bf16(o4.x, h0, l0); split_bf16(o4.y, h1, l1);
    split_bf16(o4.z, h2, l2); split_bf16(o4.w, h3, l3);
    *(__nv_bfloat162*)(Yh + base + tid*4)     = __halves2bfloat162(h0, h1);
    *(__nv_bfloat162*)(Yh + base + tid*4 + 2) = __halves2bfloat162(h2, h3);
    *(__nv_bfloat162*)(Yl + base + tid*4)     = __halves2bfloat162(l0, l1);
    *(__nv_bfloat162*)(Yl + base + tid*4 + 2) = __halves2bfloat162(l2, l3);
}

// ============== mma.sync bf16-split GEMM: C = epi(A@B^T + bias) =============
#define ASZ (128 * RSTR)
#define SA_HI 0
#define SA_LO ASZ
#define SB_HI (2*ASZ)
#define SB_LO (3*ASZ)
#define GEMM_SMEM (4*ASZ)         // 73728 B

template<int OUTM, bool RELU, bool RES>
__global__ __launch_bounds__(256)
void gemm_mma(
    const __nv_bfloat16* __restrict__ Ah, const __nv_bfloat16* __restrict__ Al,
    const __nv_bfloat16* __restrict__ Bh, const __nv_bfloat16* __restrict__ Bl,
    const float* __restrict__ bias, const float* __restrict__ res,
    float* __restrict__ Cf, __nv_bfloat16* __restrict__ Ch,
    __nv_bfloat16* __restrict__ Cl, int N, int K, float scale)
{
    extern __shared__ char smem[];
    uint32_t sb = smem_u32(smem);
    int tid = threadIdx.x;
    int lane = tid & 31, wid = tid >> 5;
    int wm = wid & 3, wn = wid >> 2;
    int m0 = blockIdx.y * 128, n0 = blockIdx.x * 128;

    int aRow = wm * 32 + ((lane >> 3) & 1) * 8 + (lane & 7);
    uint32_t aOff = (uint32_t)aRow * RSTR + ((lane >> 4) & 1) * 16;
    int bRow = wn * 64 + ((lane >> 4) & 1) * 8 + (lane & 7);
    uint32_t bOff = (uint32_t)bRow * RSTR + ((lane >> 3) & 1) * 16;

    float acc[2][8][4] = {};

    const int chunks = K >> 6;
    for (int c = 0; c < chunks; c++) {
        size_t koff = (size_t)c * 64;
        #pragma unroll
        for (int i = 0; i < 4; i++) {
            int u = tid + i * 256;
            int row = u >> 3, seg = u & 7;
            uint32_t d = (uint32_t)row * RSTR + seg * 16;
            *(uint4*)(smem + SA_HI + d) = *((const uint4*)(Ah + (size_t)(m0+row)*K + koff) + seg);
            *(uint4*)(smem + SA_LO + d) = *((const uint4*)(Al + (size_t)(m0+row)*K + koff) + seg);
            *(uint4*)(smem + SB_HI + d) = *((const uint4*)(Bh + (size_t)(n0+row)*K + koff) + seg);
            *(uint4*)(smem + SB_LO + d) = *((const uint4*)(Bl + (size_t)(n0+row)*K + koff) + seg);
        }
        __syncthreads();

        #pragma unroll
        for (int kk = 0; kk < 4; kk++) {
            uint32_t kb = kk * 32;
            uint32_t ah[2][4], al[2][4];
            ldsm4(ah[0], sb + SA_HI + aOff + kb);
            ldsm4(ah[1], sb + SA_HI + aOff + 16*RSTR + kb);
            ldsm4(al[0], sb + SA_LO + aOff + kb);
            ldsm4(al[1], sb + SA_LO + aOff + 16*RSTR + kb);
            uint32_t bh[4][4], bl[4][4];
            #pragma unroll
            for (int jp = 0; jp < 4; jp++) {
                ldsm4(bh[jp], sb + SB_HI + bOff + (uint32_t)jp*16*RSTR + kb);
                ldsm4(bl[jp], sb + SB_LO + bOff + (uint32_t)jp*16*RSTR + kb);
            }
            #pragma unroll
            for (int im = 0; im < 2; im++)
                #pragma unroll
                for (int jn = 0; jn < 8; jn++) {
                    const uint32_t* ph = &bh[jn >> 1][(jn & 1) * 2];
                    const uint32_t* pl = &bl[jn >> 1][(jn & 1) * 2];
                    mma_bf16(acc[im][jn], ah[im], ph);
                    mma_bf16(acc[im][jn], ah[im], pl);
                    mma_bf16(acc[im][jn], al[im], ph);
                }
        }
        __syncthreads();
    }

    int r = lane >> 2, cc = (lane & 3) * 2;
    #pragma unroll
    for (int im = 0; im < 2; im++) {
        int rg0 = m0 + wm * 32 + im * 16 + r;
        #pragma unroll
        for (int jn = 0; jn < 8; jn++) {
            int col = n0 + wn * 64 + jn * 8 + cc;
            float2 bv = *(const float2*)(bias + col);
            float v0 = (acc[im][jn][0] + bv.x) * scale;
            float v1 = (acc[im][jn][1] + bv.y) * scale;
            float v2 = (acc[im][jn][2] + bv.x) * scale;
            float v3 = (acc[im][jn][3] + bv.y) * scale;
            if (RELU) {
                v0 = fmaxf(v0, 0.f); v1 = fmaxf(v1, 0.f);
                v2 = fmaxf(v2, 0.f); v3 = fmaxf(v3, 0.f);
            }
            size_t o0 = (size_t)rg0 * N + col;
            size_t o1 = (size_t)(rg0 + 8) * N + col;
            if (RES) {
                float2 r0 = *(const float2*)(res + o0);
                float2 r1 = *(const float2*)(res + o1);
                v0 += r0.x; v1 += r0.y; v2 += r1.x; v3 += r1.y;
            }
            if (OUTM == 0) {
                *(float2*)(Cf + o0) = make_float2(v0, v1);
                *(float2*)(Cf + o1) = make_float2(v2, v3);
            } else {
                __nv_bfloat16 h0,l0,h1,l1,h2,l2,h3,l3;
                split_bf16(v0, h0, l0); split_bf16(v1, h1, l1);
                split_bf16(v2, h2, l2); split_bf16(v3, h3, l3);
                *(__nv_bfloat162*)(Ch + o0) = __halves2bfloat162(h0, h1);
                *(__nv_bfloat162*)(Ch + o1) = __halves2bfloat162(h2, h3);
                *(__nv_bfloat162*)(Cl + o0) = __halves2bfloat162(l0, l1);
                *(__nv_bfloat162*)(Cl + o1) = __halves2bfloat162(l2, l3);
            }
        }
    }
}

// ========== rel = q @ Er^T, band tiles only (K = 64) ========================
__global__ __launch_bounds__(256)
void rel_mma(
    const __nv_bfloat16* __restrict__ Ah, const __nv_bfloat16* __restrict__ Al,
    const __nv_bfloat16* __restrict__ Bh, const __nv_bfloat16* __restrict__ Bl,
    float* __restrict__ out)
{
    int m0 = blockIdx.y * 128, n0 = blockIdx.x * 128;
    if (m0 + n0 + 255 < SS - 1) return;   // tile never read by skew gather
    int bh = blockIdx.z;
    int b = bh >> 4, h = bh & 15;

    extern __shared__ char smem[];
    uint32_t sb = smem_u32(smem);
    int tid = threadIdx.x;
    int lane = tid & 31, wid = tid >> 5;
    int wm = wid & 3, wn = wid >> 2;

    const __nv_bfloat16* Ahp = Ah + ((size_t)b * SS) * DD + h * DH;
    const __nv_bfloat16* Alp = Al + ((size_t)b * SS) * DD + h * DH;

    #pragma unroll
    for (int i = 0; i < 4; i++) {
        int u = tid + i * 256;
        int row = u >> 3, seg = u & 7;
        uint32_t d = (uint32_t)row * RSTR + seg * 16;
        *(uint4*)(smem + SA_HI + d) = *((const uint4*)(Ahp + (size_t)(m0+row)*DD) + seg);
        *(uint4*)(smem + SA_LO + d) = *((const uint4*)(Alp + (size_t)(m0+row)*DD) + seg);
        *(uint4*)(smem + SB_HI + d) = *((const uint4*)(Bh + (size_t)(n0+row)*DH) + seg);
        *(uint4*)(smem + SB_LO + d) = *((const uint4*)(Bl + (size_t)(n0+row)*DH) + seg);
    }
    __syncthreads();

    int aRow = wm * 32 + ((lane >> 3) & 1) * 8 + (lane & 7);
    uint32_t aOff = (uint32_t)aRow * RSTR + ((lane >> 4) & 1) * 16;
    int bRow = wn * 64 + ((lane >> 4) & 1) * 8 + (lane & 7);
    uint32_t bOff = (uint32_t)bRow * RSTR + ((lane >> 3) & 1) * 16;

    float acc[2][8][4] = {};
    #pragma unroll
    for (int kk = 0; kk < 4; kk++) {
        uint32_t kb = kk * 32;
        uint32_t ah[2][4], al[2][4];
        ldsm4(ah[0], sb + SA_HI + aOff + kb);
        ldsm4(ah[1], sb + SA_HI + aOff + 16*RSTR + kb);
        ldsm4(al[0], sb + SA_LO + aOff + kb);
        ldsm4(al[1], sb + SA_LO + aOff + 16*RSTR + kb);
        uint32_t bhf[4][4], blf[4][4];
        #pragma unroll
        for (int jp = 0; jp < 4; jp++) {
            ldsm4(bhf[jp], sb + SB_HI + bOff + (uint32_t)jp*16*RSTR + kb);
            ldsm4(blf[jp], sb + SB_LO + bOff + (uint32_t)jp*16*RSTR + kb);
        }
        #pragma unroll
        for (int im = 0; im < 2; im++)
            #pragma unroll
            for (int jn = 0; jn < 8; jn++) {
                const uint32_t* ph = &bhf[jn >> 1][(jn & 1) * 2];
                const uint32_t* pl = &blf[jn >> 1][(jn & 1) * 2];
                mma_bf16(acc[im][jn], ah[im], ph);
                mma_bf16(acc[im][jn], ah[im], pl);
                mma_bf16(acc[im][jn], al[im], ph);
            }
    }

    float* ob = out + (size_t)bh * SS * SS;
    int r = lane >> 2, cc = (lane & 3) * 2;
    #pragma unroll
    for (int im = 0; im < 2; im++) {
        int rg0 = m0 + wm * 32 + im * 16 + r;
        #pragma unroll
        for (int jn = 0; jn < 8; jn++) {
            int col = n0 + wn * 64 + jn * 8 + cc;
            *(float2*)(ob + (size_t)rg0 * SS + col)      = make_float2(acc[im][jn][0], acc[im][jn][1]);
            *(float2*)(ob + (size_t)(rg0+8) * SS + col)  = make_float2(acc[im][jn][2], acc[im][jn][3]);
        }
    }
}

// ========== flash attention: softmax(qk^T + skew(rel)) @ v ==================
// CTA: one (b,h) and 128 q-rows. 8 warps x 16 rows. Chunks of 128 t-cols.
#define FL_Q_HI 0
#define FL_Q_LO (ASZ)
#define FL_K_HI (2*ASZ)
#define FL_K_LO (3*ASZ)
#define FL_V_HI (4*ASZ)
#define FL_V_LO (5*ASZ)
#define FL_SMEM (6*ASZ)    // 110592 B

__global__ __launch_bounds__(256)
void flash_mma(
    const __nv_bfloat16* __restrict__ Qh, const __nv_bfloat16* __restrict__ Ql,
    const __nv_bfloat16* __restrict__ Kh, const __nv_bfloat16* __restrict__ Kl,
    const __nv_bfloat16* __restrict__ Vh, const __nv_bfloat16* __restrict__ Vl,
    const float* __restrict__ REL,
    __nv_bfloat16* __restrict__ Oh, __nv_bfloat16* __restrict__ Ol)
{
    extern __shared__ char smem[];
    uint32_t sb = smem_u32(smem);
    int tid = threadIdx.x;
    int lane = tid & 31, w = tid >> 5;
    int s0 = blockIdx.x * 128;
    int bh = blockIdx.y;
    int b = bh >> 4, h = bh & 15;

    const __nv_bfloat16* qhb = Qh + ((size_t)b * SS) * DD + h * DH;
    const __nv_bfloat16* qlb = Ql + ((size_t)b * SS) * DD + h * DH;
    const __nv_bfloat16* khb = Kh + ((size_t)b * SS) * DD + h * DH;
    const __nv_bfloat16* klb = Kl + ((size_t)b * SS) * DD + h * DH;
    const __nv_bfloat16* vhb = Vh + ((size_t)b * SS) * DD + h * DH;
    const __nv_bfloat16* vlb = Vl + ((size_t)b * SS) * DD + h * DH;

    // stage Q (persistent in smem)
    #pragma unroll
    for (int i = 0; i < 4; i++) {
        int u = tid + i * 256;
        int row = u >> 3, seg = u & 7;
        uint32_t d = (uint32_t)row * RSTR + seg * 16;
        *(uint4*)(smem + FL_Q_HI + d) = *((const uint4*)(qhb + (size_t)(s0+row)*DD) + seg);
        *(uint4*)(smem + FL_Q_LO + d) = *((const uint4*)(qlb + (size_t)(s0+row)*DD) + seg);
    }

    int g = lane >> 2, qd = lane & 3;
    int sA = s0 + w * 16 + g;
    int sB = sA + 8;
    const float* rpA = REL + ((size_t)bh * SS + sA) * SS + (SS - 1 - sA);
    const float* rpB = REL + ((size_t)bh * SS + sB) * SS + (SS - 1 - sB);

    uint32_t aOff = (uint32_t)(w*16 + ((lane>>3)&1)*8 + (lane&7)) * RSTR + ((lane>>4)&1)*16;
    uint32_t bOff = (uint32_t)(((lane>>4)&1)*8 + (lane&7)) * RSTR + ((lane>>3)&1)*16;
    uint32_t vKr = ((lane>>3)&1)*8 + (lane&7);
    uint32_t vCb = ((lane>>4)&1)*16;

    float oacc[8][4] = {};
    float mA = -1e30f, mB = -1e30f, lA = 0.f, lB = 0.f;

    for (int c = 0; c < SS/128; c++) {
        int t0 = c * 128;
        __syncthreads();    // protect K/V smem reuse (and Q store on c==0)
        #pragma unroll
        for (int i = 0; i < 4; i++) {
            int u = tid + i * 256;
            int row = u >> 3, seg = u & 7;
            uint32_t d = (uint32_t)row * RSTR + seg * 16;
            *(uint4*)(smem + FL_K_HI + d) = *((const uint4*)(khb + (size_t)(t0+row)*DD) + seg);
            *(uint4*)(smem + FL_K_LO + d) = *((const uint4*)(klb + (size_t)(t0+row)*DD) + seg);
            *(uint4*)(smem + FL_V_HI + d) = *((const uint4*)(vhb + (size_t)(t0+row)*DD) + seg);
            *(uint4*)(smem + FL_V_LO + d) = *((const uint4*)(vlb + (size_t)(t0+row)*DD) + seg);
        }
        __syncthreads();

        // S = q @ k^T (3-term split), 16 n-tiles of 8 cols
        float sacc[16][4] = {};
        #pragma unroll
        for (int kk = 0; kk < 4; kk++) {
            uint32_t kb = kk * 32;
            uint32_t ah[4], al[4];
            ldsm4(ah, sb + FL_Q_HI + aOff + kb);
            ldsm4(al, sb + FL_Q_LO + aOff + kb);
            #pragma unroll
            for (int jp = 0; jp < 8; jp++) {
                uint32_t bhf[4], blf[4];
                ldsm4(bhf, sb + FL_K_HI + bOff + (uint32_t)jp*16*RSTR + kb);
                ldsm4(blf, sb + FL_K_LO + bOff + (uint32_t)jp*16*RSTR + kb);
                #pragma unroll
                for (int e = 0; e < 2; e++) {
                    int jn = jp * 2 + e;
                    mma_bf16(sacc[jn], ah, &bhf[e*2]);
                    mma_bf16(sacc[jn], ah, &blf[e*2]);
                    mma_bf16(sacc[jn], al, &bhf[e*2]);
                }
            }
        }

        // skew add: sacc[jn][0,1] row sA, [2,3] row sB, cols t0+8jn+2qd(+1)
        if (t0 <= sA) {
            #pragma unroll
            for (int jn = 0; jn < 16; jn++) {
                int t = t0 + jn * 8 + qd * 2;
                if (t     <= sA) sacc[jn][0] += __ldg(rpA + t);
                if (t + 1 <= sA) sacc[jn][1] += __ldg(rpA + t + 1);
            }
        }
        if (t0 <= sB) {
            #pragma unroll
            for (int jn = 0; jn < 16; jn++) {
                int t = t0 + jn * 8 + qd * 2;
                if (t     <= sB) sacc[jn][2] += __ldg(rpB + t);
                if (t + 1 <= sB) sacc[jn][3] += __ldg(rpB + t + 1);
            }
        }

        // online softmax: row max over chunk
        float cmA = -1e30f, cmB = -1e30f;
        #pragma unroll
        for (int jn = 0; jn < 16; jn++) {
            cmA = fmaxf(cmA, fmaxf(sacc[jn][0], sacc[jn][1]));
            cmB = fmaxf(cmB, fmaxf(sacc[jn][2], sacc[jn][3]));
        }
        cmA = fmaxf(cmA, __shfl_xor_sync(0xFFFFFFFF, cmA, 1));
        cmA = fmaxf(cmA, __shfl_xor_sync(0xFFFFFFFF, cmA, 2));
        cmB = fmaxf(cmB, __shfl_xor_sync(0xFFFFFFFF, cmB, 1));
        cmB = fmaxf(cmB, __shfl_xor_sync(0xFFFFFFFF, cmB, 2));
        float mnA = fmaxf(mA, cmA), mnB = fmaxf(mB, cmB);
        float alA = __expf(mA - mnA), alB = __expf(mB - mnB);
        mA = mnA; mB = mnB;

        float suA = 0.f, suB = 0.f;
        #pragma unroll
        for (int jn = 0; jn < 16; jn++) {
            sacc[jn][0] = __expf(sacc[jn][0] - mnA);
            sacc[jn][1] = __expf(sacc[jn][1] - mnA);
            sacc[jn][2] = __expf(sacc[jn][2] - mnB);
            sacc[jn][3] = __expf(sacc[jn][3] - mnB);
            suA += sacc[jn][0] + sacc[jn][1];
            suB += sacc[jn][2] + sacc[jn][3];
        }
        suA += __shfl_xor_sync(0xFFFFFFFF, suA, 1);
        suA += __shfl_xor_sync(0xFFFFFFFF, suA, 2);
        suB += __shfl_xor_sync(0xFFFFFFFF, suB, 1);
        suB += __shfl_xor_sync(0xFFFFFFFF, suB, 2);
        lA = lA * alA + suA;
        lB = lB * alB + suB;

        // rescale O
        #pragma unroll
        for (int jn = 0; jn < 8; jn++) {
            oacc[jn][0] *= alA; oacc[jn][1] *= alA;
            oacc[jn][2] *= alB; oacc[jn][3] *= alB;
        }

        // O += P @ V (3-term), 8 k-steps of 16
        #pragma unroll
        for (int k2 = 0; k2 < 8; k2++) {
            uint32_t pah[4], pal[4];
            pack_split(sacc[2*k2][0],   sacc[2*k2][1],   pah[0], pal[0]);
            pack_split(sacc[2*k2][2],   sacc[2*k2][3],   pah[1], pal[1]);
            pack_split(sacc[2*k2+1][0], sacc[2*k2+1][1], pah[2], pal[2]);
            pack_split(sacc[2*k2+1][2], sacc[2*k2+1][3], pah[3], pal[3]);
            uint32_t vRowOff = (uint32_t)(k2 * 16 + vKr) * RSTR;
            #pragma unroll
            for (int jp = 0; jp < 4; jp++) {
                uint32_t vh4[4], vl4[4];
                ldsm4t(vh4, sb + FL_V_HI + vRowOff + vCb + jp * 32);
                ldsm4t(vl4, sb + FL_V_LO + vRowOff + vCb + jp * 32);
                #pragma unroll
                for (int e = 0; e < 2; e++) {
                    int jo = jp * 2 + e;
                    mma_bf16(oacc[jo], pah, &vh4[e*2]);
                    mma_bf16(oacc[jo], pah, &vl4[e*2]);
                    mma_bf16(oacc[jo], pal, &vh4[e*2]);
                }
            }
        }
    }

    // epilogue: normalize + split store
    float invA = 1.f / lA, invB = 1.f / lB;
    #pragma unroll
    for (int jn = 0; jn < 8; jn++) {
        int col = h * DH + jn * 8 + qd * 2;
        size_t oA = ((size_t)b * SS + sA) * DD + col;
        size_t oB = ((size_t)b * SS + sB) * DD + col;
        __nv_bfloat16 h0,l0,h1,l1;
        split_bf16(oacc[jn][0] * invA, h0, l0);
        split_bf16(oacc[jn][1] * invA, h1, l1);
        *(__nv_bfloat162*)(Oh + oA) = __halves2bfloat162(h0, h1);
        *(__nv_bfloat162*)(Ol + oA) = __halves2bfloat162(l0, l1);
        split_bf16(oacc[jn][2] * invB, h0, l0);
        split_bf16(oacc[jn][3] * invB, h1, l1);
        *(__nv_bfloat162*)(Oh + oB) = __halves2bfloat162(h0, h1);
        *(__nv_bfloat162*)(Ol + oB) = __halves2bfloat162(l0, l1);
    }
}

// ---------------- launch ----------------------------------------------------
extern "C" void kernel_launch(void* const* d_in, const int* in_sizes, int n_in,
                              void* d_out, int out_size)
{
    (void)in_sizes; (void)n_in; (void)out_size;
    const float* x   = (const float*)d_in[0];
    const float* Wq  = (const float*)d_in[1];
    const float* bq  = (const float*)d_in[2];
    const float* Wk  = (const float*)d_in[3];
    const float* bk  = (const float*)d_in[4];
    const float* Wv  = (const float*)d_in[5];
    const float* bv  = (const float*)d_in[6];
    const float* Wo  = (const float*)d_in[7];
    const float* bo  = (const float*)d_in[8];
    const float* Er  = (const float*)d_in[9];
    const float* W1  = (const float*)d_in[10];
    const float* b1  = (const float*)d_in[11];
    const float* W2  = (const float*)d_in[12];
    const float* b2  = (const float*)d_in[13];
    const float* g1  = (const float*)d_in[14];
    const float* be1 = (const float*)d_in[15];
    const float* g2  = (const float*)d_in[16];
    const float* be2 = (const float*)d_in[17];
    float* y = (float*)d_out;

    float *px1, *prel, *px2, *px3;
    cudaGetSymbolAddress((void**)&px1,  g_x1);
    cudaGetSymbolAddress((void**)&prel, g_rel);
    cudaGetSymbolAddress((void**)&px2,  g_x2);
    cudaGetSymbolAddress((void**)&px3,  g_x3);

    __nv_bfloat16 *x1h,*x1l,*x3h,*x3l,*qh,*ql,*kh,*kl,*vh,*vl,*avh,*avl,*h1h,*h1l,*erh,*erl;
    __nv_bfloat16 *wqh,*wql,*wkh,*wkl,*wvh,*wvl,*woh,*wol,*w1h,*w1l,*w2h,*w2l;
    cudaGetSymbolAddress((void**)&x1h, g_x1h); cudaGetSymbolAddress((void**)&x1l, g_x1l);
    cudaGetSymbolAddress((void**)&x3h, g_x3h); cudaGetSymbolAddress((void**)&x3l, g_x3l);
    cudaGetSymbolAddress((void**)&qh,  g_qh);  cudaGetSymbolAddress((void**)&ql,  g_ql);
    cudaGetSymbolAddress((void**)&kh,  g_kh);  cudaGetSymbolAddress((void**)&kl,  g_kl);
    cudaGetSymbolAddress((void**)&vh,  g_vh);  cudaGetSymbolAddress((void**)&vl,  g_vl);
    cudaGetSymbolAddress((void**)&avh, g_avh); cudaGetSymbolAddress((void**)&avl, g_avl);
    cudaGetSymbolAddress((void**)&h1h, g_h1h); cudaGetSymbolAddress((void**)&h1l, g_h1l);
    cudaGetSymbolAddress((void**)&erh, g_erh); cudaGetSymbolAddress((void**)&erl, g_erl);
    cudaGetSymbolAddress((void**)&wqh, g_wqh); cudaGetSymbolAddress((void**)&wql, g_wql);
    cudaGetSymbolAddress((void**)&wkh, g_wkh); cudaGetSymbolAddress((void**)&wkl, g_wkl);
    cudaGetSymbolAddress((void**)&wvh, g_wvh); cudaGetSymbolAddress((void**)&wvl, g_wvl);
    cudaGetSymbolAddress((void**)&woh, g_woh); cudaGetSymbolAddress((void**)&wol, g_wol);
    cudaGetSymbolAddress((void**)&w1h, g_w1h); cudaGetSymbolAddress((void**)&w1l, g_w1l);
    cudaGetSymbolAddress((void**)&w2h, g_w2h); cudaGetSymbolAddress((void**)&w2l, g_w2l);

    cudaFuncSetAttribute(gemm_mma<0,false,true>,  cudaFuncAttributeMaxDynamicSharedMemorySize, GEMM_SMEM);
    cudaFuncSetAttribute(gemm_mma<1,false,false>, cudaFuncAttributeMaxDynamicSharedMemorySize, GEMM_SMEM);
    cudaFuncSetAttribute(gemm_mma<1,true,false>,  cudaFuncAttributeMaxDynamicSharedMemorySize, GEMM_SMEM);
    cudaFuncSetAttribute(rel_mma,   cudaFuncAttributeMaxDynamicSharedMemorySize, GEMM_SMEM);
    cudaFuncSetAttribute(flash_mma, cudaFuncAttributeMaxDynamicSharedMemorySize, FL_SMEM);

    // weight transpose + split
    convBT<<<dim3(DD/32, DD/32), 256>>>(Wq, wqh, wql, DD, DD);
    convBT<<<dim3(DD/32, DD/32), 256>>>(Wk, wkh, wkl, DD, DD);
    convBT<<<dim3(DD/32, DD/32), 256>>>(Wv, wvh, wvl, DD, DD);
    convBT<<<dim3(DD/32, DD/32), 256>>>(Wo, woh, wol, DD, DD);
    convBT<<<dim3(FF/32, DD/32), 256>>>(W1, w1h, w1l, DD, FF);
    convBT<<<dim3(DD/32, FF/32), 256>>>(W2, w2h, w2l, FF, DD);
    splitE<<<(SS*DH + 1023)/1024, 256>>>(Er, erh, erl, SS*DH);

    // x1 = LN(x)
    ln_kernel<<<MM, 256>>>(x, g1, be1, px1, x1h, x1l);
    // q/k/v -> bf16 hi/lo
    gemm_mma<1,false,false><<<dim3(DD/128, MM/128), 256, GEMM_SMEM>>>(
        x1h, x1l, wqh, wql, bq, nullptr, nullptr, qh, ql, DD, DD, 0.125f);
    gemm_mma<1,false,false><<<dim3(DD/128, MM/128), 256, GEMM_SMEM>>>(
        x1h, x1l, wkh, wkl, bk, nullptr, nullptr, kh, kl, DD, DD, 1.f);
    gemm_mma<1,false,false><<<dim3(DD/128, MM/128), 256, GEMM_SMEM>>>(
        x1h, x1l, wvh, wvl, bv, nullptr, nullptr, vh, vl, DD, DD, 1.f);
    // rel = q@Er^T (band tiles)
    rel_mma<<<dim3(SS/128, SS/128, BB*HH), 256, GEMM_SMEM>>>(qh, ql, erh, erl, prel);
    // fused attention
    flash_mma<<<dim3(SS/128, BB*HH), 256, FL_SMEM>>>(
        qh, ql, kh, kl, vh, vl, prel, avh, avl);
    // x2 = x1 + av@Wo + bo
    gemm_mma<0,false,true><<<dim3(DD/128, MM/128), 256, GEMM_SMEM>>>(
        avh, avl, woh, wol, bo, px1, px2, nullptr, nullptr, DD, DD, 1.f);
    // x3 = LN(x2)
    ln_kernel<<<MM, 256>>>(px2, g2, be2, px3, x3h, x3l);
    // h1 = relu(x3@W1+b1)
    gemm_mma<1,true,false><<<dim3(FF/128, MM/128), 256, GEMM_SMEM>>>(
        x3h, x3l, w1h, w1l, b1, nullptr, nullptr, h1h, h1l, FF, DD, 1.f);
    // y = x3 + h1@W2 + b2
    gemm_mma<0,false,true><<<dim3(DD/128, MM/128), 256, GEMM_SMEM>>>(
        h1h, h1l, w2h, w2l, b2, px3, y, nullptr, nullptr, DD, FF, 1.f);
}